// round 12
// baseline (speedup 1.0000x reference)
#include <cuda_runtime.h>

#define N_NODES    100000
#define N_EDGES    3200000
#define NUM_GRAPHS 128
#define HID        64
#define IN_DIM     15
#define NBLK       ((N_NODES + 255) / 256)   // scan blocks
#define NPB        96                        // nodes per linear block

// ---------------- scratch (device globals; no allocation allowed) -----------
// hs: 32 x bf16x2 per node (64 cols). +1 zero pad row for OOB gather lanes.
__device__ __align__(16) unsigned g_hs[(N_NODES + 1) * 32];
__device__ __align__(16) float    g_aggA[N_NODES * HID];
__device__ __align__(16) float    g_aggB[N_NODES * HID];
__device__ int   g_csrc [N_EDGES];   // CSR (by dst): source node per slot
__device__ int   g_edeg  [N_NODES];
__device__ int   g_pre   [N_NODES];
__device__ int   g_rowptr[N_NODES];
__device__ int   g_fill  [N_NODES];
__device__ int   g_bsum[NBLK];
__device__ int   g_boff[NBLK];
__device__ float g_dis[N_NODES];
__device__ float g_cnt[NUM_GRAPHS];
__device__ int   g_e32;
__device__ int   g_b32;

// ---------------- dtype detection -------------------------------------------
__global__ void gnn_detect(const void* edges, const void* batch) {
    __shared__ int se, sb;
    if (threadIdx.x == 0) { se = 0; sb = 0; }
    __syncthreads();
    for (int i = threadIdx.x; i < 2048; i += 256) {
        long long vi = (long long)i * (N_EDGES / 2048);
        long long v = ((const long long*)edges)[vi];
        if (v < 0 || v >= N_NODES) { atomicOr(&se, 1); break; }
    }
    for (int i = threadIdx.x; i < 2048; i += 256) {
        long long vi = (long long)i * ((N_NODES / 2) / 2048);
        long long v = ((const long long*)batch)[vi];
        if (v < 0 || v >= NUM_GRAPHS) { atomicOr(&sb, 1); break; }
    }
    __syncthreads();
    if (threadIdx.x == 0) { g_e32 = se; g_b32 = sb; }
}

__device__ __forceinline__ int batch_at(const void* batch, int v) {
    return g_b32 ? ((const int*)batch)[v] : (int)((const long long*)batch)[v];
}

// ---------------- degree / normalization ------------------------------------
__global__ void gnn_deg_zero() {
    int v = blockIdx.x * blockDim.x + threadIdx.x;
    if (v < N_NODES) g_edeg[v] = 0;
    if (blockIdx.x == 0 && threadIdx.x < 32)   // zero the gather pad row
        g_hs[N_NODES * 32 + threadIdx.x] = 0u;
}

// 4 edges per thread, vectorized index loads.
__global__ void gnn_deg_count(const void* __restrict__ edges) {
    int i = blockIdx.x * blockDim.x + threadIdx.x;
    if (i >= N_EDGES / 4) return;
    if (g_e32) {
        int4 d = ((const int4*)((const int*)edges + N_EDGES))[i];
        atomicAdd(&g_edeg[d.x], 1);
        atomicAdd(&g_edeg[d.y], 1);
        atomicAdd(&g_edeg[d.z], 1);
        atomicAdd(&g_edeg[d.w], 1);
    } else {
        const longlong2* e2 = (const longlong2*)((const long long*)edges + N_EDGES);
        longlong2 a = e2[i * 2];
        longlong2 b = e2[i * 2 + 1];
        atomicAdd(&g_edeg[(int)a.x], 1);
        atomicAdd(&g_edeg[(int)a.y], 1);
        atomicAdd(&g_edeg[(int)b.x], 1);
        atomicAdd(&g_edeg[(int)b.y], 1);
    }
}

__global__ void gnn_dis() {
    int v = blockIdx.x * blockDim.x + threadIdx.x;
    if (v < N_NODES) {
        float d = (float)(g_edeg[v] + 1);  // + self loop
        g_dis[v] = rsqrtf(d);
    }
}

// ---------------- exclusive scan of g_edeg -> g_rowptr -----------------------
__global__ void gnn_scan1() {
    __shared__ int s[256];
    int t = threadIdx.x;
    int i = blockIdx.x * 256 + t;
    int v = (i < N_NODES) ? g_edeg[i] : 0;
    s[t] = v; __syncthreads();
    for (int off = 1; off < 256; off <<= 1) {
        int add = (t >= off) ? s[t - off] : 0;
        __syncthreads();
        s[t] += add;
        __syncthreads();
    }
    if (i < N_NODES) g_pre[i] = s[t] - v;
    if (t == 255) g_bsum[blockIdx.x] = s[255];
}

__global__ void gnn_scan2() {
    __shared__ int s[512];
    int t = threadIdx.x;
    int v = (t < NBLK) ? g_bsum[t] : 0;
    s[t] = v; __syncthreads();
    for (int off = 1; off < 512; off <<= 1) {
        int add = (t >= off) ? s[t - off] : 0;
        __syncthreads();
        s[t] += add;
        __syncthreads();
    }
    if (t < NBLK) g_boff[t] = s[t] - v;
}

__global__ void gnn_scan3() {
    int i = blockIdx.x * blockDim.x + threadIdx.x;
    if (i < N_NODES) {
        g_rowptr[i] = g_pre[i] + g_boff[blockIdx.x];
        g_fill[i]   = 0;
    }
}

// ---------------- CSR fill (4 edges/thread, vectorized) ----------------------
__global__ void gnn_csr_fill(const void* __restrict__ edges) {
    int i = blockIdx.x * blockDim.x + threadIdx.x;
    if (i >= N_EDGES / 4) return;
    int s0, s1, s2, s3, d0, d1, d2, d3;
    if (g_e32) {
        int4 s = ((const int4*)edges)[i];
        int4 d = ((const int4*)((const int*)edges + N_EDGES))[i];
        s0 = s.x; s1 = s.y; s2 = s.z; s3 = s.w;
        d0 = d.x; d1 = d.y; d2 = d.z; d3 = d.w;
    } else {
        const longlong2* es2 = (const longlong2*)edges;
        longlong2 sa = es2[i * 2], sb = es2[i * 2 + 1];
        const longlong2* ed2 = (const longlong2*)((const long long*)edges + N_EDGES);
        longlong2 da = ed2[i * 2], db = ed2[i * 2 + 1];
        s0 = (int)sa.x; s1 = (int)sa.y; s2 = (int)sb.x; s3 = (int)sb.y;
        d0 = (int)da.x; d1 = (int)da.y; d2 = (int)db.x; d3 = (int)db.y;
    }
    g_csrc[g_rowptr[d0] + atomicAdd(&g_fill[d0], 1)] = s0;
    g_csrc[g_rowptr[d1] + atomicAdd(&g_fill[d1], 1)] = s1;
    g_csrc[g_rowptr[d2] + atomicAdd(&g_fill[d2], 1)] = s2;
    g_csrc[g_rowptr[d3] + atomicAdd(&g_fill[d3], 1)] = s3;
}

// ---------------- linear: hs[v] = bf16((relu(in+b_prev) @ W) * dis[v]) -------
// EXACT R11 body.
template <int K, bool PRE>
__global__ void __launch_bounds__(256) gnn_linear(const float* __restrict__ in,
                                                  const float* __restrict__ W,
                                                  const float* __restrict__ bias_prev,
                                                  unsigned* __restrict__ hs) {
    __shared__ float Wsh[K * HID];
    __shared__ float insh[K * 97];
    __shared__ float bsh[K];
    const int tid  = threadIdx.x;
    const int base = blockIdx.x * NPB;

    for (int i = tid; i < K * HID; i += 256) Wsh[i] = W[i];
    if (PRE) for (int i = tid; i < K; i += 256) bsh[i] = bias_prev[i];
    __syncthreads();

    for (int i = tid; i < NPB * K; i += 256) {
        int n = i / K;
        int k = i - n * K;
        int v = base + n;
        float val = 0.0f;
        if (v < N_NODES) {
            val = in[v * K + k];
            if (PRE) val = fmaxf(val + bsh[k], 0.0f);
        }
        insh[k * 97 + n] = val;
    }
    __syncthreads();

    const int ng = tid >> 3;          // 0..31 node groups of 3
    const int cb = (tid & 7) * 8;     // col block
    float acc[3][8];
#pragma unroll
    for (int i = 0; i < 3; i++)
#pragma unroll
        for (int j = 0; j < 8; j++) acc[i][j] = 0.0f;

#pragma unroll 8
    for (int k = 0; k < K; k++) {
        float4 w0 = *(const float4*)&Wsh[k * HID + cb];
        float4 w1 = *(const float4*)&Wsh[k * HID + cb + 4];
#pragma unroll
        for (int i = 0; i < 3; i++) {
            float a = insh[k * 97 + ng * 3 + i];
            acc[i][0] = fmaf(a, w0.x, acc[i][0]);
            acc[i][1] = fmaf(a, w0.y, acc[i][1]);
            acc[i][2] = fmaf(a, w0.z, acc[i][2]);
            acc[i][3] = fmaf(a, w0.w, acc[i][3]);
            acc[i][4] = fmaf(a, w1.x, acc[i][4]);
            acc[i][5] = fmaf(a, w1.y, acc[i][5]);
            acc[i][6] = fmaf(a, w1.z, acc[i][6]);
            acc[i][7] = fmaf(a, w1.w, acc[i][7]);
        }
    }

#pragma unroll
    for (int i = 0; i < 3; i++) {
        int v = base + ng * 3 + i;
        if (v < N_NODES) {
            float ds = g_dis[v];
#pragma unroll
            for (int j = 0; j < 4; j++) {
                float fl = acc[i][2 * j]     * ds;   // even col -> low half
                float fh = acc[i][2 * j + 1] * ds;   // odd col  -> high half
                unsigned r;
                asm("cvt.rn.bf16x2.f32 %0, %1, %2;" : "=r"(r) : "f"(fh), "f"(fl));
                hs[v * 32 + (cb >> 1) + j] = r;
            }
        }
    }
}

// ---------------- gather: agg[v] = dis[v] * (sum_e hs[src] + hs[v]) ----------
// EXACT R11 body: warp per node, 4 subgroups x 8 lanes, LDG.128 per 4 edges.
__global__ void __launch_bounds__(256) gnn_gather(const uint4* __restrict__ hs4,
                                                  float4* __restrict__ agg4) {
    int warp = (blockIdx.x * blockDim.x + threadIdx.x) >> 5;
    int lane = threadIdx.x & 31;
    if (warp >= N_NODES) return;
    const int v  = warp;
    const int sg = lane >> 3;   // subgroup 0..3 (edge slot within quad)
    const int p  = lane & 7;    // 16B-chunk position within row
    const int beg = g_rowptr[v];
    const int end = beg + g_edeg[v];

    float acc[8];
#pragma unroll
    for (int i = 0; i < 8; i++) acc[i] = 0.0f;

    // self term: only subgroup 0 accumulates row v (once)
    {
        uint4 hv = hs4[v * 8 + p];
        if (sg == 0) {
            acc[0] += __uint_as_float(hv.x << 16);
            acc[1] += __uint_as_float(hv.x & 0xffff0000u);
            acc[2] += __uint_as_float(hv.y << 16);
            acc[3] += __uint_as_float(hv.y & 0xffff0000u);
            acc[4] += __uint_as_float(hv.z << 16);
            acc[5] += __uint_as_float(hv.z & 0xffff0000u);
            acc[6] += __uint_as_float(hv.w << 16);
            acc[7] += __uint_as_float(hv.w & 0xffff0000u);
        }
    }

    for (int base = beg; base < end; base += 32) {
        int idx = base + lane;
        int s = (idx < end) ? g_csrc[idx] : N_NODES;   // pad row (zeros) if OOB
        const int iters = (min(32, end - base) + 3) >> 2;  // warp-uniform
#pragma unroll
        for (int j = 0; j < 8; j++) {
            if (j < iters) {
                int ss = __shfl_sync(0xffffffffu, s, j * 4 + sg);
                uint4 hh = hs4[ss * 8 + p];
                acc[0] += __uint_as_float(hh.x << 16);
                acc[1] += __uint_as_float(hh.x & 0xffff0000u);
                acc[2] += __uint_as_float(hh.y << 16);
                acc[3] += __uint_as_float(hh.y & 0xffff0000u);
                acc[4] += __uint_as_float(hh.z << 16);
                acc[5] += __uint_as_float(hh.z & 0xffff0000u);
                acc[6] += __uint_as_float(hh.w << 16);
                acc[7] += __uint_as_float(hh.w & 0xffff0000u);
            }
        }
    }

    // combine subgroups: butterfly over lanes 8 and 16 apart
#pragma unroll
    for (int i = 0; i < 8; i++) {
        acc[i] += __shfl_xor_sync(0xffffffffu, acc[i], 8);
        acc[i] += __shfl_xor_sync(0xffffffffu, acc[i], 16);
    }

    float ds = g_dis[v];
    if (sg == 0) {   // lanes 0..7 write cols 8p..8p+7
        float4 r0 = make_float4(acc[0] * ds, acc[1] * ds, acc[2] * ds, acc[3] * ds);
        float4 r1 = make_float4(acc[4] * ds, acc[5] * ds, acc[6] * ds, acc[7] * ds);
        agg4[v * 16 + p * 2]     = r0;
        agg4[v * 16 + p * 2 + 1] = r1;
    }
}

// ---------------- pooling ----------------------------------------------------
__global__ void gnn_zero_out(float* __restrict__ out) {
    int i = blockIdx.x * blockDim.x + threadIdx.x;
    if (i < NUM_GRAPHS * HID) out[i] = 0.0f;
    if (i < NUM_GRAPHS) g_cnt[i] = 0.0f;
}

__global__ void gnn_pool(const float4* __restrict__ agg,
                         const float4* __restrict__ bias4,
                         const void* __restrict__ batch,
                         float* __restrict__ out) {
    unsigned idx = blockIdx.x * blockDim.x + threadIdx.x;
    int v = idx >> 4;
    int c = idx & 15;
    if (v >= N_NODES) return;
    int g = batch_at(batch, v);
    float4 a = agg[v * 16 + c];
    float4 b = bias4[c];
    float x0 = fmaxf(a.x + b.x, 0.0f);
    float x1 = fmaxf(a.y + b.y, 0.0f);
    float x2 = fmaxf(a.z + b.z, 0.0f);
    float x3 = fmaxf(a.w + b.w, 0.0f);
    float* p = &out[g * HID + c * 4];
    asm volatile("red.global.add.v4.f32 [%0], {%1, %2, %3, %4};"
                 :: "l"(p), "f"(x0), "f"(x1), "f"(x2), "f"(x3)
                 : "memory");
    if (c == 0) atomicAdd(&g_cnt[g], 1.0f);
}

__global__ void gnn_div(float* __restrict__ out) {
    int i = blockIdx.x * blockDim.x + threadIdx.x;
    if (i < NUM_GRAPHS * HID) {
        int g = i >> 6;
        out[i] /= fmaxf(g_cnt[g], 1.0f);
    }
}

// ---------------- host -------------------------------------------------------
extern "C" void kernel_launch(void* const* d_in, const int* in_sizes, int n_in,
                              void* d_out, int out_size) {
    const float* x     = (const float*)d_in[0];
    const float* w1    = (const float*)d_in[1];
    const float* b1    = (const float*)d_in[2];
    const float* w2    = (const float*)d_in[3];
    const float* b2    = (const float*)d_in[4];
    const float* w3    = (const float*)d_in[5];
    const float* b3    = (const float*)d_in[6];
    const float* w4    = (const float*)d_in[7];
    const float* b4    = (const float*)d_in[8];
    const void*  edges = d_in[9];
    const void*  batch = d_in[10];
    float* out = (float*)d_out;

    void *p_hs, *p_aggA, *p_aggB;
    cudaGetSymbolAddress(&p_hs,   g_hs);
    cudaGetSymbolAddress(&p_aggA, g_aggA);
    cudaGetSymbolAddress(&p_aggB, g_aggB);
    unsigned* hs   = (unsigned*)p_hs;
    float*    aggA = (float*)p_aggA;
    float*    aggB = (float*)p_aggB;

    const int TB = 256;
    const int nodeB  = (N_NODES + TB - 1) / TB;
    const int edge4B = (N_EDGES / 4 + TB - 1) / TB;

    gnn_detect   <<<1, 256>>>(edges, batch);
    gnn_deg_zero <<<nodeB, TB>>>();
    gnn_deg_count<<<edge4B, TB>>>(edges);
    gnn_dis      <<<nodeB, TB>>>();
    gnn_scan1    <<<NBLK, 256>>>();
    gnn_scan2    <<<1, 512>>>();
    gnn_scan3    <<<NBLK, 256>>>();
    gnn_csr_fill <<<edge4B, TB>>>(edges);

    const int linB = (N_NODES + NPB - 1) / NPB;
    const int gatB = (N_NODES * 32 + TB - 1) / TB;

    // layer 1
    gnn_linear<IN_DIM, false><<<linB, TB>>>(x, w1, nullptr, hs);
    gnn_gather<<<gatB, TB>>>((const uint4*)hs, (float4*)aggA);
    // layer 2
    gnn_linear<HID, true><<<linB, TB>>>(aggA, w2, b1, hs);
    gnn_gather<<<gatB, TB>>>((const uint4*)hs, (float4*)aggB);
    // layer 3
    gnn_linear<HID, true><<<linB, TB>>>(aggB, w3, b2, hs);
    gnn_gather<<<gatB, TB>>>((const uint4*)hs, (float4*)aggA);
    // layer 4
    gnn_linear<HID, true><<<linB, TB>>>(aggA, w4, b3, hs);
    gnn_gather<<<gatB, TB>>>((const uint4*)hs, (float4*)aggB);

    // pooling
    gnn_zero_out<<<(NUM_GRAPHS * HID + TB - 1) / TB, TB>>>(out);
    const unsigned poolT = (unsigned)N_NODES * 16u;
    gnn_pool<<<(int)((poolT + TB - 1) / TB), TB>>>(
        (const float4*)aggB, (const float4*)b4, batch, out);
    gnn_div<<<(NUM_GRAPHS * HID + TB - 1) / TB, TB>>>(out);
}

// round 13
// speedup vs baseline: 1.0132x; 1.0132x over previous
#include <cuda_runtime.h>

#define N_NODES    100000
#define N_EDGES    3200000
#define NUM_GRAPHS 128
#define HID        64
#define IN_DIM     15
#define NBLK       ((N_NODES + 255) / 256)   // scan blocks
#define NPB        96                        // nodes per linear block

// ---------------- scratch (device globals; no allocation allowed) -----------
// hs: 32 x bf16x2 per node (64 cols). +1 zero pad row for OOB gather lanes.
__device__ __align__(16) unsigned g_hs[(N_NODES + 1) * 32];
__device__ __align__(16) float    g_aggA[N_NODES * HID];
__device__ __align__(16) float    g_aggB[N_NODES * HID];
__device__ int   g_csrc [N_EDGES];   // CSR (by dst): source node per slot
__device__ int   g_edeg  [N_NODES];
__device__ int   g_pre   [N_NODES];
__device__ int   g_rowptr[N_NODES];
__device__ int   g_fill  [N_NODES];
__device__ int   g_bsum[NBLK];
__device__ int   g_boff[NBLK];
__device__ float g_dis[N_NODES];
__device__ float g_cnt[NUM_GRAPHS];
__device__ int   g_e32;
__device__ int   g_b32;

// ---------------- packed f32x2 helpers ---------------------------------------
__device__ __forceinline__ unsigned long long fma2(unsigned long long a,
                                                   unsigned long long b,
                                                   unsigned long long c) {
    unsigned long long d;
    asm("fma.rn.f32x2 %0, %1, %2, %3;" : "=l"(d) : "l"(a), "l"(b), "l"(c));
    return d;
}
__device__ __forceinline__ unsigned long long pack2(float x) {
    unsigned long long d;
    asm("mov.b64 %0, {%1, %1};" : "=l"(d) : "f"(x));
    return d;
}

// ---------------- dtype detection -------------------------------------------
__global__ void gnn_detect(const void* edges, const void* batch) {
    __shared__ int se, sb;
    if (threadIdx.x == 0) { se = 0; sb = 0; }
    __syncthreads();
    for (int i = threadIdx.x; i < 2048; i += 256) {
        long long vi = (long long)i * (N_EDGES / 2048);
        long long v = ((const long long*)edges)[vi];
        if (v < 0 || v >= N_NODES) { atomicOr(&se, 1); break; }
    }
    for (int i = threadIdx.x; i < 2048; i += 256) {
        long long vi = (long long)i * ((N_NODES / 2) / 2048);
        long long v = ((const long long*)batch)[vi];
        if (v < 0 || v >= NUM_GRAPHS) { atomicOr(&sb, 1); break; }
    }
    __syncthreads();
    if (threadIdx.x == 0) { g_e32 = se; g_b32 = sb; }
}

__device__ __forceinline__ int edge_at(const void* edges, long long i) {
    return g_e32 ? ((const int*)edges)[i] : (int)((const long long*)edges)[i];
}
__device__ __forceinline__ int batch_at(const void* batch, int v) {
    return g_b32 ? ((const int*)batch)[v] : (int)((const long long*)batch)[v];
}

// ---------------- degree / normalization ------------------------------------
__global__ void gnn_deg_zero() {
    int v = blockIdx.x * blockDim.x + threadIdx.x;
    if (v < N_NODES) g_edeg[v] = 0;
    if (blockIdx.x == 0 && threadIdx.x < 32)   // zero the gather pad row
        g_hs[N_NODES * 32 + threadIdx.x] = 0u;
}

__global__ void gnn_deg_count(const void* __restrict__ edges) {
    int e = blockIdx.x * blockDim.x + threadIdx.x;
    if (e < N_EDGES) {
        int d = edge_at(edges, (long long)N_EDGES + e);
        atomicAdd(&g_edeg[d], 1);
    }
}

__global__ void gnn_dis() {
    int v = blockIdx.x * blockDim.x + threadIdx.x;
    if (v < N_NODES) {
        float d = (float)(g_edeg[v] + 1);  // + self loop
        g_dis[v] = rsqrtf(d);
    }
}

// ---------------- exclusive scan of g_edeg -> g_rowptr -----------------------
__global__ void gnn_scan1() {
    __shared__ int s[256];
    int t = threadIdx.x;
    int i = blockIdx.x * 256 + t;
    int v = (i < N_NODES) ? g_edeg[i] : 0;
    s[t] = v; __syncthreads();
    for (int off = 1; off < 256; off <<= 1) {
        int add = (t >= off) ? s[t - off] : 0;
        __syncthreads();
        s[t] += add;
        __syncthreads();
    }
    if (i < N_NODES) g_pre[i] = s[t] - v;
    if (t == 255) g_bsum[blockIdx.x] = s[255];
}

__global__ void gnn_scan2() {
    __shared__ int s[512];
    int t = threadIdx.x;
    int v = (t < NBLK) ? g_bsum[t] : 0;
    s[t] = v; __syncthreads();
    for (int off = 1; off < 512; off <<= 1) {
        int add = (t >= off) ? s[t - off] : 0;
        __syncthreads();
        s[t] += add;
        __syncthreads();
    }
    if (t < NBLK) g_boff[t] = s[t] - v;
}

__global__ void gnn_scan3() {
    int i = blockIdx.x * blockDim.x + threadIdx.x;
    if (i < N_NODES) {
        g_rowptr[i] = g_pre[i] + g_boff[blockIdx.x];
        g_fill[i]   = 0;
    }
}

// ---------------- CSR fill ----------------------------------------------------
__global__ void gnn_csr_fill(const void* __restrict__ edges) {
    int e = blockIdx.x * blockDim.x + threadIdx.x;
    if (e < N_EDGES) {
        int s = edge_at(edges, e);
        int d = edge_at(edges, (long long)N_EDGES + e);
        int slot = g_rowptr[d] + atomicAdd(&g_fill[d], 1);
        g_csrc[slot] = s;
    }
}

// ---------------- linear: hs[v] = bf16((relu(in+b_prev) @ W) * dis[v]) -------
// 256 threads, 96 nodes/block, 3 nodes/thread, 8 cols/thread.
// Packed f32x2 FMA (half the FFMA issue). insh node-major rows, stride padded
// to avoid bank conflicts on the float4 a-loads (SR=68 for K=64, 20 for K=15).
template <int K, bool PRE>
__global__ void __launch_bounds__(256) gnn_linear(const float* __restrict__ in,
                                                  const float* __restrict__ W,
                                                  const float* __restrict__ bias_prev,
                                                  unsigned* __restrict__ hs) {
    constexpr int SR = (K == 64) ? 68 : 20;   // padded row stride (words)
    constexpr int K4 = K / 4;
    __shared__ float Wsh[K * HID];
    __shared__ float insh[NPB * SR];
    __shared__ float bsh[K];
    const int tid  = threadIdx.x;
    const int base = blockIdx.x * NPB;

    for (int i = tid; i < K * HID; i += 256) Wsh[i] = W[i];
    if (PRE) for (int i = tid; i < K; i += 256) bsh[i] = bias_prev[i];
    __syncthreads();

    for (int i = tid; i < NPB * K; i += 256) {
        int n = i / K;
        int k = i - n * K;
        int v = base + n;
        float val = 0.0f;
        if (v < N_NODES) {
            val = in[v * K + k];
            if (PRE) val = fmaxf(val + bsh[k], 0.0f);
        }
        insh[n * SR + k] = val;
    }
    __syncthreads();

    const int ng = tid >> 3;          // 0..31, 3 nodes each
    const int cb = (tid & 7) * 8;     // col block (8 cols = 4 packed pairs)
    unsigned long long accp[3][4];
#pragma unroll
    for (int i = 0; i < 3; i++)
#pragma unroll
        for (int j = 0; j < 4; j++) accp[i][j] = 0ull;

#pragma unroll
    for (int k4 = 0; k4 < K4; k4++) {
        float4 a0 = *(const float4*)&insh[(ng * 3 + 0) * SR + k4 * 4];
        float4 a1 = *(const float4*)&insh[(ng * 3 + 1) * SR + k4 * 4];
        float4 a2 = *(const float4*)&insh[(ng * 3 + 2) * SR + k4 * 4];
#pragma unroll
        for (int t = 0; t < 4; t++) {
            int k = k4 * 4 + t;
            ulonglong2 w0 = *(const ulonglong2*)&Wsh[k * HID + cb];
            ulonglong2 w1 = *(const ulonglong2*)&Wsh[k * HID + cb + 4];
            float av0 = (t == 0) ? a0.x : (t == 1) ? a0.y : (t == 2) ? a0.z : a0.w;
            float av1 = (t == 0) ? a1.x : (t == 1) ? a1.y : (t == 2) ? a1.z : a1.w;
            float av2 = (t == 0) ? a2.x : (t == 1) ? a2.y : (t == 2) ? a2.z : a2.w;
            unsigned long long p0 = pack2(av0), p1 = pack2(av1), p2 = pack2(av2);
            accp[0][0] = fma2(p0, w0.x, accp[0][0]);
            accp[0][1] = fma2(p0, w0.y, accp[0][1]);
            accp[0][2] = fma2(p0, w1.x, accp[0][2]);
            accp[0][3] = fma2(p0, w1.y, accp[0][3]);
            accp[1][0] = fma2(p1, w0.x, accp[1][0]);
            accp[1][1] = fma2(p1, w0.y, accp[1][1]);
            accp[1][2] = fma2(p1, w1.x, accp[1][2]);
            accp[1][3] = fma2(p1, w1.y, accp[1][3]);
            accp[2][0] = fma2(p2, w0.x, accp[2][0]);
            accp[2][1] = fma2(p2, w0.y, accp[2][1]);
            accp[2][2] = fma2(p2, w1.x, accp[2][2]);
            accp[2][3] = fma2(p2, w1.y, accp[2][3]);
        }
    }
#pragma unroll
    for (int k = K4 * 4; k < K; k++) {   // K tail (K=15 only)
        ulonglong2 w0 = *(const ulonglong2*)&Wsh[k * HID + cb];
        ulonglong2 w1 = *(const ulonglong2*)&Wsh[k * HID + cb + 4];
#pragma unroll
        for (int i = 0; i < 3; i++) {
            unsigned long long p = pack2(insh[(ng * 3 + i) * SR + k]);
            accp[i][0] = fma2(p, w0.x, accp[i][0]);
            accp[i][1] = fma2(p, w0.y, accp[i][1]);
            accp[i][2] = fma2(p, w1.x, accp[i][2]);
            accp[i][3] = fma2(p, w1.y, accp[i][3]);
        }
    }

#pragma unroll
    for (int i = 0; i < 3; i++) {
        int v = base + ng * 3 + i;
        if (v < N_NODES) {
            float ds = g_dis[v];
#pragma unroll
            for (int j = 0; j < 4; j++) {
                unsigned long long p = accp[i][j];
                float fl = __uint_as_float((unsigned)(p & 0xffffffffull)) * ds;
                float fh = __uint_as_float((unsigned)(p >> 32)) * ds;
                unsigned r;
                asm("cvt.rn.bf16x2.f32 %0, %1, %2;" : "=r"(r) : "f"(fh), "f"(fl));
                hs[v * 32 + (cb >> 1) + j] = r;
            }
        }
    }
}

// ---------------- gather: agg[v] = dis[v] * (sum_e hs[src] + hs[v]) ----------
// EXACT R11 body: warp per node, 4 subgroups x 8 lanes, LDG.128 per 4 edges.
__global__ void __launch_bounds__(256) gnn_gather(const uint4* __restrict__ hs4,
                                                  float4* __restrict__ agg4) {
    int warp = (blockIdx.x * blockDim.x + threadIdx.x) >> 5;
    int lane = threadIdx.x & 31;
    if (warp >= N_NODES) return;
    const int v  = warp;
    const int sg = lane >> 3;   // subgroup 0..3 (edge slot within quad)
    const int p  = lane & 7;    // 16B-chunk position within row
    const int beg = g_rowptr[v];
    const int end = beg + g_edeg[v];

    float acc[8];
#pragma unroll
    for (int i = 0; i < 8; i++) acc[i] = 0.0f;

    // self term: only subgroup 0 accumulates row v (once)
    {
        uint4 hv = hs4[v * 8 + p];
        if (sg == 0) {
            acc[0] += __uint_as_float(hv.x << 16);
            acc[1] += __uint_as_float(hv.x & 0xffff0000u);
            acc[2] += __uint_as_float(hv.y << 16);
            acc[3] += __uint_as_float(hv.y & 0xffff0000u);
            acc[4] += __uint_as_float(hv.z << 16);
            acc[5] += __uint_as_float(hv.z & 0xffff0000u);
            acc[6] += __uint_as_float(hv.w << 16);
            acc[7] += __uint_as_float(hv.w & 0xffff0000u);
        }
    }

    for (int base = beg; base < end; base += 32) {
        int idx = base + lane;
        int s = (idx < end) ? g_csrc[idx] : N_NODES;   // pad row (zeros) if OOB
        const int iters = (min(32, end - base) + 3) >> 2;  // warp-uniform
#pragma unroll
        for (int j = 0; j < 8; j++) {
            if (j < iters) {
                int ss = __shfl_sync(0xffffffffu, s, j * 4 + sg);
                uint4 hh = hs4[ss * 8 + p];
                acc[0] += __uint_as_float(hh.x << 16);
                acc[1] += __uint_as_float(hh.x & 0xffff0000u);
                acc[2] += __uint_as_float(hh.y << 16);
                acc[3] += __uint_as_float(hh.y & 0xffff0000u);
                acc[4] += __uint_as_float(hh.z << 16);
                acc[5] += __uint_as_float(hh.z & 0xffff0000u);
                acc[6] += __uint_as_float(hh.w << 16);
                acc[7] += __uint_as_float(hh.w & 0xffff0000u);
            }
        }
    }

    // combine subgroups: butterfly over lanes 8 and 16 apart
#pragma unroll
    for (int i = 0; i < 8; i++) {
        acc[i] += __shfl_xor_sync(0xffffffffu, acc[i], 8);
        acc[i] += __shfl_xor_sync(0xffffffffu, acc[i], 16);
    }

    float ds = g_dis[v];
    if (sg == 0) {   // lanes 0..7 write cols 8p..8p+7
        float4 r0 = make_float4(acc[0] * ds, acc[1] * ds, acc[2] * ds, acc[3] * ds);
        float4 r1 = make_float4(acc[4] * ds, acc[5] * ds, acc[6] * ds, acc[7] * ds);
        agg4[v * 16 + p * 2]     = r0;
        agg4[v * 16 + p * 2 + 1] = r1;
    }
}

// ---------------- pooling ----------------------------------------------------
__global__ void gnn_zero_out(float* __restrict__ out) {
    int i = blockIdx.x * blockDim.x + threadIdx.x;
    if (i < NUM_GRAPHS * HID) out[i] = 0.0f;
    if (i < NUM_GRAPHS) g_cnt[i] = 0.0f;
}

__global__ void gnn_pool(const float4* __restrict__ agg,
                         const float4* __restrict__ bias4,
                         const void* __restrict__ batch,
                         float* __restrict__ out) {
    unsigned idx = blockIdx.x * blockDim.x + threadIdx.x;
    int v = idx >> 4;
    int c = idx & 15;
    if (v >= N_NODES) return;
    int g = batch_at(batch, v);
    float4 a = agg[v * 16 + c];
    float4 b = bias4[c];
    float x0 = fmaxf(a.x + b.x, 0.0f);
    float x1 = fmaxf(a.y + b.y, 0.0f);
    float x2 = fmaxf(a.z + b.z, 0.0f);
    float x3 = fmaxf(a.w + b.w, 0.0f);
    float* p = &out[g * HID + c * 4];
    asm volatile("red.global.add.v4.f32 [%0], {%1, %2, %3, %4};"
                 :: "l"(p), "f"(x0), "f"(x1), "f"(x2), "f"(x3)
                 : "memory");
    if (c == 0) atomicAdd(&g_cnt[g], 1.0f);
}

__global__ void gnn_div(float* __restrict__ out) {
    int i = blockIdx.x * blockDim.x + threadIdx.x;
    if (i < NUM_GRAPHS * HID) {
        int g = i >> 6;
        out[i] /= fmaxf(g_cnt[g], 1.0f);
    }
}

// ---------------- host -------------------------------------------------------
extern "C" void kernel_launch(void* const* d_in, const int* in_sizes, int n_in,
                              void* d_out, int out_size) {
    const float* x     = (const float*)d_in[0];
    const float* w1    = (const float*)d_in[1];
    const float* b1    = (const float*)d_in[2];
    const float* w2    = (const float*)d_in[3];
    const float* b2    = (const float*)d_in[4];
    const float* w3    = (const float*)d_in[5];
    const float* b3    = (const float*)d_in[6];
    const float* w4    = (const float*)d_in[7];
    const float* b4    = (const float*)d_in[8];
    const void*  edges = d_in[9];
    const void*  batch = d_in[10];
    float* out = (float*)d_out;

    void *p_hs, *p_aggA, *p_aggB;
    cudaGetSymbolAddress(&p_hs,   g_hs);
    cudaGetSymbolAddress(&p_aggA, g_aggA);
    cudaGetSymbolAddress(&p_aggB, g_aggB);
    unsigned* hs   = (unsigned*)p_hs;
    float*    aggA = (float*)p_aggA;
    float*    aggB = (float*)p_aggB;

    const int TB = 256;
    const int nodeB = (N_NODES + TB - 1) / TB;
    const int edgeB = (N_EDGES + TB - 1) / TB;

    gnn_detect   <<<1, 256>>>(edges, batch);
    gnn_deg_zero <<<nodeB, TB>>>();
    gnn_deg_count<<<edgeB, TB>>>(edges);
    gnn_dis      <<<nodeB, TB>>>();
    gnn_scan1    <<<NBLK, 256>>>();
    gnn_scan2    <<<1, 512>>>();
    gnn_scan3    <<<NBLK, 256>>>();
    gnn_csr_fill <<<edgeB, TB>>>(edges);

    const int linB = (N_NODES + NPB - 1) / NPB;
    const int gatB = (N_NODES * 32 + TB - 1) / TB;

    // layer 1
    gnn_linear<IN_DIM, false><<<linB, TB>>>(x, w1, nullptr, hs);
    gnn_gather<<<gatB, TB>>>((const uint4*)hs, (float4*)aggA);
    // layer 2
    gnn_linear<HID, true><<<linB, TB>>>(aggA, w2, b1, hs);
    gnn_gather<<<gatB, TB>>>((const uint4*)hs, (float4*)aggB);
    // layer 3
    gnn_linear<HID, true><<<linB, TB>>>(aggB, w3, b2, hs);
    gnn_gather<<<gatB, TB>>>((const uint4*)hs, (float4*)aggA);
    // layer 4
    gnn_linear<HID, true><<<linB, TB>>>(aggA, w4, b3, hs);
    gnn_gather<<<gatB, TB>>>((const uint4*)hs, (float4*)aggB);

    // pooling
    gnn_zero_out<<<(NUM_GRAPHS * HID + TB - 1) / TB, TB>>>(out);
    const unsigned poolT = (unsigned)N_NODES * 16u;
    gnn_pool<<<(int)((poolT + TB - 1) / TB), TB>>>(
        (const float4*)aggB, (const float4*)b4, batch, out);
    gnn_div<<<(NUM_GRAPHS * HID + TB - 1) / TB, TB>>>(out);
}

// round 14
// speedup vs baseline: 1.0476x; 1.0340x over previous
#include <cuda_runtime.h>

#define N_NODES    100000
#define N_EDGES    3200000
#define NUM_GRAPHS 128
#define HID        64
#define IN_DIM     15
#define NBLK       ((N_NODES + 255) / 256)   // scan blocks
#define NPB        96                        // nodes per linear block

// ---------------- scratch (device globals; no allocation allowed) -----------
// hs: 32 x bf16x2 per node (64 cols). +1 zero pad row for OOB gather lanes.
__device__ __align__(16) unsigned g_hs[(N_NODES + 1) * 32];
// xs: 8 x bf16x2 per node (16 cols, 15 real). +1 zero pad row.
__device__ __align__(16) unsigned g_xs[(N_NODES + 1) * 8];
__device__ __align__(16) float    g_aggA[N_NODES * HID];
__device__ __align__(16) float    g_aggB[N_NODES * HID];
__device__ int   g_csrc [N_EDGES];   // CSR (by dst): source node per slot
__device__ int   g_edeg  [N_NODES];
__device__ int   g_pre   [N_NODES];
__device__ int   g_rowptr[N_NODES];
__device__ int   g_fill  [N_NODES];
__device__ int   g_bsum[NBLK];
__device__ int   g_boff[NBLK];
__device__ float g_dis[N_NODES];
__device__ float g_cnt[NUM_GRAPHS];
__device__ int   g_e32;
__device__ int   g_b32;

// ---------------- packed f32x2 helpers ---------------------------------------
__device__ __forceinline__ unsigned long long fma2(unsigned long long a,
                                                   unsigned long long b,
                                                   unsigned long long c) {
    unsigned long long d;
    asm("fma.rn.f32x2 %0, %1, %2, %3;" : "=l"(d) : "l"(a), "l"(b), "l"(c));
    return d;
}
__device__ __forceinline__ unsigned long long pack2(float x) {
    unsigned long long d;
    asm("mov.b64 %0, {%1, %1};" : "=l"(d) : "f"(x));
    return d;
}

// ---------------- dtype detection -------------------------------------------
__global__ void gnn_detect(const void* edges, const void* batch) {
    __shared__ int se, sb;
    if (threadIdx.x == 0) { se = 0; sb = 0; }
    __syncthreads();
    for (int i = threadIdx.x; i < 2048; i += 256) {
        long long vi = (long long)i * (N_EDGES / 2048);
        long long v = ((const long long*)edges)[vi];
        if (v < 0 || v >= N_NODES) { atomicOr(&se, 1); break; }
    }
    for (int i = threadIdx.x; i < 2048; i += 256) {
        long long vi = (long long)i * ((N_NODES / 2) / 2048);
        long long v = ((const long long*)batch)[vi];
        if (v < 0 || v >= NUM_GRAPHS) { atomicOr(&sb, 1); break; }
    }
    __syncthreads();
    if (threadIdx.x == 0) { g_e32 = se; g_b32 = sb; }
}

__device__ __forceinline__ int edge_at(const void* edges, long long i) {
    return g_e32 ? ((const int*)edges)[i] : (int)((const long long*)edges)[i];
}
__device__ __forceinline__ int batch_at(const void* batch, int v) {
    return g_b32 ? ((const int*)batch)[v] : (int)((const long long*)batch)[v];
}

// ---------------- degree / normalization ------------------------------------
__global__ void gnn_deg_zero() {
    int v = blockIdx.x * blockDim.x + threadIdx.x;
    if (v < N_NODES) g_edeg[v] = 0;
    if (blockIdx.x == 0 && threadIdx.x < 32)   // zero hs pad row
        g_hs[N_NODES * 32 + threadIdx.x] = 0u;
    if (blockIdx.x == 1 && threadIdx.x < 8)    // zero xs pad row
        g_xs[N_NODES * 8 + threadIdx.x] = 0u;
}

__global__ void gnn_deg_count(const void* __restrict__ edges) {
    int e = blockIdx.x * blockDim.x + threadIdx.x;
    if (e < N_EDGES) {
        int d = edge_at(edges, (long long)N_EDGES + e);
        atomicAdd(&g_edeg[d], 1);
    }
}

__global__ void gnn_dis() {
    int v = blockIdx.x * blockDim.x + threadIdx.x;
    if (v < N_NODES) {
        float d = (float)(g_edeg[v] + 1);  // + self loop
        g_dis[v] = rsqrtf(d);
    }
}

// ---------------- xs pack: xs[v] = bf16(x[v] * dis[v]), 16 cols ---------------
__global__ void gnn_xs(const float* __restrict__ x) {
    int v = blockIdx.x * blockDim.x + threadIdx.x;
    if (v >= N_NODES) return;
    float ds = g_dis[v];
    unsigned r[8];
#pragma unroll
    for (int j = 0; j < 8; j++) {
        float a = x[v * IN_DIM + 2 * j] * ds;
        float b = (2 * j + 1 < IN_DIM) ? x[v * IN_DIM + 2 * j + 1] * ds : 0.0f;
        asm("cvt.rn.bf16x2.f32 %0, %1, %2;" : "=r"(r[j]) : "f"(b), "f"(a));
    }
    uint4* dst = (uint4*)&g_xs[v * 8];
    dst[0] = make_uint4(r[0], r[1], r[2], r[3]);
    dst[1] = make_uint4(r[4], r[5], r[6], r[7]);
}

// ---------------- exclusive scan of g_edeg -> g_rowptr -----------------------
__global__ void gnn_scan1() {
    __shared__ int s[256];
    int t = threadIdx.x;
    int i = blockIdx.x * 256 + t;
    int v = (i < N_NODES) ? g_edeg[i] : 0;
    s[t] = v; __syncthreads();
    for (int off = 1; off < 256; off <<= 1) {
        int add = (t >= off) ? s[t - off] : 0;
        __syncthreads();
        s[t] += add;
        __syncthreads();
    }
    if (i < N_NODES) g_pre[i] = s[t] - v;
    if (t == 255) g_bsum[blockIdx.x] = s[255];
}

__global__ void gnn_scan2() {
    __shared__ int s[512];
    int t = threadIdx.x;
    int v = (t < NBLK) ? g_bsum[t] : 0;
    s[t] = v; __syncthreads();
    for (int off = 1; off < 512; off <<= 1) {
        int add = (t >= off) ? s[t - off] : 0;
        __syncthreads();
        s[t] += add;
        __syncthreads();
    }
    if (t < NBLK) g_boff[t] = s[t] - v;
}

__global__ void gnn_scan3() {
    int i = blockIdx.x * blockDim.x + threadIdx.x;
    if (i < N_NODES) {
        g_rowptr[i] = g_pre[i] + g_boff[blockIdx.x];
        g_fill[i]   = 0;
    }
}

// ---------------- CSR fill ----------------------------------------------------
__global__ void gnn_csr_fill(const void* __restrict__ edges) {
    int e = blockIdx.x * blockDim.x + threadIdx.x;
    if (e < N_EDGES) {
        int s = edge_at(edges, e);
        int d = edge_at(edges, (long long)N_EDGES + e);
        int slot = g_rowptr[d] + atomicAdd(&g_fill[d], 1);
        g_csrc[slot] = s;
    }
}

// ---------------- linear (f32x2 packed FMA, template modes) ------------------
// K: inner dim; INS: input row stride; PRE: apply bias_prev+relu on input;
// F32OUT: write fp32 64-dim rows (no dis scale) instead of bf16 messages.
template <int K, int INS, bool PRE, bool F32OUT>
__global__ void __launch_bounds__(256) gnn_linear(const float* __restrict__ in,
                                                  const float* __restrict__ W,
                                                  const float* __restrict__ bias_prev,
                                                  unsigned* __restrict__ hs) {
    constexpr int SR = (K == 64) ? 68 : 20;   // padded row stride (words)
    constexpr int K4 = K / 4;
    __shared__ float Wsh[K * HID];
    __shared__ float insh[NPB * SR];
    __shared__ float bsh[K];
    const int tid  = threadIdx.x;
    const int base = blockIdx.x * NPB;

    for (int i = tid; i < K * HID; i += 256) Wsh[i] = W[i];
    if (PRE) for (int i = tid; i < K; i += 256) bsh[i] = bias_prev[i];
    __syncthreads();

    for (int i = tid; i < NPB * K; i += 256) {
        int n = i / K;
        int k = i - n * K;
        int v = base + n;
        float val = 0.0f;
        if (v < N_NODES) {
            val = in[v * INS + k];
            if (PRE) val = fmaxf(val + bsh[k], 0.0f);
        }
        insh[n * SR + k] = val;
    }
    __syncthreads();

    const int ng = tid >> 3;          // 0..31, 3 nodes each
    const int cb = (tid & 7) * 8;     // col block (8 cols = 4 packed pairs)
    unsigned long long accp[3][4];
#pragma unroll
    for (int i = 0; i < 3; i++)
#pragma unroll
        for (int j = 0; j < 4; j++) accp[i][j] = 0ull;

#pragma unroll
    for (int k4 = 0; k4 < K4; k4++) {
        float4 a0 = *(const float4*)&insh[(ng * 3 + 0) * SR + k4 * 4];
        float4 a1 = *(const float4*)&insh[(ng * 3 + 1) * SR + k4 * 4];
        float4 a2 = *(const float4*)&insh[(ng * 3 + 2) * SR + k4 * 4];
#pragma unroll
        for (int t = 0; t < 4; t++) {
            int k = k4 * 4 + t;
            ulonglong2 w0 = *(const ulonglong2*)&Wsh[k * HID + cb];
            ulonglong2 w1 = *(const ulonglong2*)&Wsh[k * HID + cb + 4];
            float av0 = (t == 0) ? a0.x : (t == 1) ? a0.y : (t == 2) ? a0.z : a0.w;
            float av1 = (t == 0) ? a1.x : (t == 1) ? a1.y : (t == 2) ? a1.z : a1.w;
            float av2 = (t == 0) ? a2.x : (t == 1) ? a2.y : (t == 2) ? a2.z : a2.w;
            unsigned long long p0 = pack2(av0), p1 = pack2(av1), p2 = pack2(av2);
            accp[0][0] = fma2(p0, w0.x, accp[0][0]);
            accp[0][1] = fma2(p0, w0.y, accp[0][1]);
            accp[0][2] = fma2(p0, w1.x, accp[0][2]);
            accp[0][3] = fma2(p0, w1.y, accp[0][3]);
            accp[1][0] = fma2(p1, w0.x, accp[1][0]);
            accp[1][1] = fma2(p1, w0.y, accp[1][1]);
            accp[1][2] = fma2(p1, w1.x, accp[1][2]);
            accp[1][3] = fma2(p1, w1.y, accp[1][3]);
            accp[2][0] = fma2(p2, w0.x, accp[2][0]);
            accp[2][1] = fma2(p2, w0.y, accp[2][1]);
            accp[2][2] = fma2(p2, w1.x, accp[2][2]);
            accp[2][3] = fma2(p2, w1.y, accp[2][3]);
        }
    }
#pragma unroll
    for (int k = K4 * 4; k < K; k++) {   // K tail (K=15 only)
        ulonglong2 w0 = *(const ulonglong2*)&Wsh[k * HID + cb];
        ulonglong2 w1 = *(const ulonglong2*)&Wsh[k * HID + cb + 4];
#pragma unroll
        for (int i = 0; i < 3; i++) {
            unsigned long long p = pack2(insh[(ng * 3 + i) * SR + k]);
            accp[i][0] = fma2(p, w0.x, accp[i][0]);
            accp[i][1] = fma2(p, w0.y, accp[i][1]);
            accp[i][2] = fma2(p, w1.x, accp[i][2]);
            accp[i][3] = fma2(p, w1.y, accp[i][3]);
        }
    }

#pragma unroll
    for (int i = 0; i < 3; i++) {
        int v = base + ng * 3 + i;
        if (v < N_NODES) {
            if (F32OUT) {
                float* o = (float*)hs;
#pragma unroll
                for (int j = 0; j < 4; j++)
                    *(unsigned long long*)&o[v * HID + cb + 2 * j] = accp[i][j];
            } else {
                float ds = g_dis[v];
#pragma unroll
                for (int j = 0; j < 4; j++) {
                    unsigned long long p = accp[i][j];
                    float fl = __uint_as_float((unsigned)(p & 0xffffffffull)) * ds;
                    float fh = __uint_as_float((unsigned)(p >> 32)) * ds;
                    unsigned r;
                    asm("cvt.rn.bf16x2.f32 %0, %1, %2;" : "=r"(r) : "f"(fh), "f"(fl));
                    hs[v * 32 + (cb >> 1) + j] = r;
                }
            }
        }
    }
}

// ---------------- gather16: aggx[v] = dis[v]*(sum_e xs[src] + xs[v]) ---------
// Warp per node; 16 subgroups x 2 lanes; 16 edges per iteration; lane loads
// one uint4 (16B) of its subgroup's 32B source row.
__global__ void __launch_bounds__(256) gnn_gather16(const uint4* __restrict__ xs4,
                                                    float4* __restrict__ aggx4) {
    int warp = (blockIdx.x * blockDim.x + threadIdx.x) >> 5;
    int lane = threadIdx.x & 31;
    if (warp >= N_NODES) return;
    const int v  = warp;
    const int sg = lane >> 1;   // subgroup 0..15 (edge slot)
    const int p  = lane & 1;    // 16B-chunk position within 32B row
    const int beg = g_rowptr[v];
    const int end = beg + g_edeg[v];

    float acc[8];
#pragma unroll
    for (int i = 0; i < 8; i++) acc[i] = 0.0f;

    {   // self term: subgroup 0 only
        uint4 hv = xs4[v * 2 + p];
        if (sg == 0) {
            acc[0] += __uint_as_float(hv.x << 16);
            acc[1] += __uint_as_float(hv.x & 0xffff0000u);
            acc[2] += __uint_as_float(hv.y << 16);
            acc[3] += __uint_as_float(hv.y & 0xffff0000u);
            acc[4] += __uint_as_float(hv.z << 16);
            acc[5] += __uint_as_float(hv.z & 0xffff0000u);
            acc[6] += __uint_as_float(hv.w << 16);
            acc[7] += __uint_as_float(hv.w & 0xffff0000u);
        }
    }

    for (int base = beg; base < end; base += 32) {
        int idx = base + lane;
        int s = (idx < end) ? g_csrc[idx] : N_NODES;   // pad row (zeros) if OOB
        const int iters = (min(32, end - base) + 15) >> 4;  // 1 or 2
#pragma unroll
        for (int j = 0; j < 2; j++) {
            if (j < iters) {
                int ss = __shfl_sync(0xffffffffu, s, j * 16 + sg);
                uint4 hh = xs4[ss * 2 + p];
                acc[0] += __uint_as_float(hh.x << 16);
                acc[1] += __uint_as_float(hh.x & 0xffff0000u);
                acc[2] += __uint_as_float(hh.y << 16);
                acc[3] += __uint_as_float(hh.y & 0xffff0000u);
                acc[4] += __uint_as_float(hh.z << 16);
                acc[5] += __uint_as_float(hh.z & 0xffff0000u);
                acc[6] += __uint_as_float(hh.w << 16);
                acc[7] += __uint_as_float(hh.w & 0xffff0000u);
            }
        }
    }

    // combine across subgroups (bits 1..4 of lane), preserving p (bit 0)
#pragma unroll
    for (int i = 0; i < 8; i++) {
        acc[i] += __shfl_xor_sync(0xffffffffu, acc[i], 2);
        acc[i] += __shfl_xor_sync(0xffffffffu, acc[i], 4);
        acc[i] += __shfl_xor_sync(0xffffffffu, acc[i], 8);
        acc[i] += __shfl_xor_sync(0xffffffffu, acc[i], 16);
    }

    float ds = g_dis[v];
    if (sg == 0) {   // lanes 0,1 write cols p*8 .. p*8+7 (row stride 16 floats)
        aggx4[v * 4 + p * 2]     = make_float4(acc[0] * ds, acc[1] * ds, acc[2] * ds, acc[3] * ds);
        aggx4[v * 4 + p * 2 + 1] = make_float4(acc[4] * ds, acc[5] * ds, acc[6] * ds, acc[7] * ds);
    }
}

// ---------------- gather (64-col bf16): EXACT R11/R13 body -------------------
__global__ void __launch_bounds__(256) gnn_gather(const uint4* __restrict__ hs4,
                                                  float4* __restrict__ agg4) {
    int warp = (blockIdx.x * blockDim.x + threadIdx.x) >> 5;
    int lane = threadIdx.x & 31;
    if (warp >= N_NODES) return;
    const int v  = warp;
    const int sg = lane >> 3;   // subgroup 0..3
    const int p  = lane & 7;    // 16B-chunk position within row
    const int beg = g_rowptr[v];
    const int end = beg + g_edeg[v];

    float acc[8];
#pragma unroll
    for (int i = 0; i < 8; i++) acc[i] = 0.0f;

    {
        uint4 hv = hs4[v * 8 + p];
        if (sg == 0) {
            acc[0] += __uint_as_float(hv.x << 16);
            acc[1] += __uint_as_float(hv.x & 0xffff0000u);
            acc[2] += __uint_as_float(hv.y << 16);
            acc[3] += __uint_as_float(hv.y & 0xffff0000u);
            acc[4] += __uint_as_float(hv.z << 16);
            acc[5] += __uint_as_float(hv.z & 0xffff0000u);
            acc[6] += __uint_as_float(hv.w << 16);
            acc[7] += __uint_as_float(hv.w & 0xffff0000u);
        }
    }

    for (int base = beg; base < end; base += 32) {
        int idx = base + lane;
        int s = (idx < end) ? g_csrc[idx] : N_NODES;
        const int iters = (min(32, end - base) + 3) >> 2;
#pragma unroll
        for (int j = 0; j < 8; j++) {
            if (j < iters) {
                int ss = __shfl_sync(0xffffffffu, s, j * 4 + sg);
                uint4 hh = hs4[ss * 8 + p];
                acc[0] += __uint_as_float(hh.x << 16);
                acc[1] += __uint_as_float(hh.x & 0xffff0000u);
                acc[2] += __uint_as_float(hh.y << 16);
                acc[3] += __uint_as_float(hh.y & 0xffff0000u);
                acc[4] += __uint_as_float(hh.z << 16);
                acc[5] += __uint_as_float(hh.z & 0xffff0000u);
                acc[6] += __uint_as_float(hh.w << 16);
                acc[7] += __uint_as_float(hh.w & 0xffff0000u);
            }
        }
    }

#pragma unroll
    for (int i = 0; i < 8; i++) {
        acc[i] += __shfl_xor_sync(0xffffffffu, acc[i], 8);
        acc[i] += __shfl_xor_sync(0xffffffffu, acc[i], 16);
    }

    float ds = g_dis[v];
    if (sg == 0) {
        float4 r0 = make_float4(acc[0] * ds, acc[1] * ds, acc[2] * ds, acc[3] * ds);
        float4 r1 = make_float4(acc[4] * ds, acc[5] * ds, acc[6] * ds, acc[7] * ds);
        agg4[v * 16 + p * 2]     = r0;
        agg4[v * 16 + p * 2 + 1] = r1;
    }
}

// ---------------- pooling ----------------------------------------------------
__global__ void gnn_zero_out(float* __restrict__ out) {
    int i = blockIdx.x * blockDim.x + threadIdx.x;
    if (i < NUM_GRAPHS * HID) out[i] = 0.0f;
    if (i < NUM_GRAPHS) g_cnt[i] = 0.0f;
}

__global__ void gnn_pool(const float4* __restrict__ agg,
                         const float4* __restrict__ bias4,
                         const void* __restrict__ batch,
                         float* __restrict__ out) {
    unsigned idx = blockIdx.x * blockDim.x + threadIdx.x;
    int v = idx >> 4;
    int c = idx & 15;
    if (v >= N_NODES) return;
    int g = batch_at(batch, v);
    float4 a = agg[v * 16 + c];
    float4 b = bias4[c];
    float x0 = fmaxf(a.x + b.x, 0.0f);
    float x1 = fmaxf(a.y + b.y, 0.0f);
    float x2 = fmaxf(a.z + b.z, 0.0f);
    float x3 = fmaxf(a.w + b.w, 0.0f);
    float* p = &out[g * HID + c * 4];
    asm volatile("red.global.add.v4.f32 [%0], {%1, %2, %3, %4};"
                 :: "l"(p), "f"(x0), "f"(x1), "f"(x2), "f"(x3)
                 : "memory");
    if (c == 0) atomicAdd(&g_cnt[g], 1.0f);
}

__global__ void gnn_div(float* __restrict__ out) {
    int i = blockIdx.x * blockDim.x + threadIdx.x;
    if (i < NUM_GRAPHS * HID) {
        int g = i >> 6;
        out[i] /= fmaxf(g_cnt[g], 1.0f);
    }
}

// ---------------- host -------------------------------------------------------
extern "C" void kernel_launch(void* const* d_in, const int* in_sizes, int n_in,
                              void* d_out, int out_size) {
    const float* x     = (const float*)d_in[0];
    const float* w1    = (const float*)d_in[1];
    const float* b1    = (const float*)d_in[2];
    const float* w2    = (const float*)d_in[3];
    const float* b2    = (const float*)d_in[4];
    const float* w3    = (const float*)d_in[5];
    const float* b3    = (const float*)d_in[6];
    const float* w4    = (const float*)d_in[7];
    const float* b4    = (const float*)d_in[8];
    const void*  edges = d_in[9];
    const void*  batch = d_in[10];
    float* out = (float*)d_out;

    void *p_hs, *p_xs, *p_aggA, *p_aggB;
    cudaGetSymbolAddress(&p_hs,   g_hs);
    cudaGetSymbolAddress(&p_xs,   g_xs);
    cudaGetSymbolAddress(&p_aggA, g_aggA);
    cudaGetSymbolAddress(&p_aggB, g_aggB);
    unsigned* hs   = (unsigned*)p_hs;
    unsigned* xs   = (unsigned*)p_xs;
    float*    aggA = (float*)p_aggA;
    float*    aggB = (float*)p_aggB;

    const int TB = 256;
    const int nodeB = (N_NODES + TB - 1) / TB;
    const int edgeB = (N_EDGES + TB - 1) / TB;

    gnn_detect   <<<1, 256>>>(edges, batch);
    gnn_deg_zero <<<nodeB, TB>>>();
    gnn_deg_count<<<edgeB, TB>>>(edges);
    gnn_dis      <<<nodeB, TB>>>();
    gnn_xs       <<<nodeB, TB>>>(x);
    gnn_scan1    <<<NBLK, 256>>>();
    gnn_scan2    <<<1, 512>>>();
    gnn_scan3    <<<NBLK, 256>>>();
    gnn_csr_fill <<<edgeB, TB>>>(edges);

    const int linB = (N_NODES + NPB - 1) / NPB;
    const int gatB = (N_NODES * 32 + TB - 1) / TB;

    // layer 1: aggx = Â·xs (16-dim, into aggB), then aggA = aggx @ W1
    gnn_gather16<<<gatB, TB>>>((const uint4*)xs, (float4*)aggB);
    gnn_linear<IN_DIM, 16, false, true><<<linB, TB>>>(aggB, w1, nullptr,
                                                      (unsigned*)aggA);
    // layer 2
    gnn_linear<HID, HID, true, false><<<linB, TB>>>(aggA, w2, b1, hs);
    gnn_gather<<<gatB, TB>>>((const uint4*)hs, (float4*)aggB);
    // layer 3
    gnn_linear<HID, HID, true, false><<<linB, TB>>>(aggB, w3, b2, hs);
    gnn_gather<<<gatB, TB>>>((const uint4*)hs, (float4*)aggA);
    // layer 4
    gnn_linear<HID, HID, true, false><<<linB, TB>>>(aggA, w4, b3, hs);
    gnn_gather<<<gatB, TB>>>((const uint4*)hs, (float4*)aggB);

    // pooling
    gnn_zero_out<<<(NUM_GRAPHS * HID + TB - 1) / TB, TB>>>(out);
    const unsigned poolT = (unsigned)N_NODES * 16u;
    gnn_pool<<<(int)((poolT + TB - 1) / TB), TB>>>(
        (const float4*)aggB, (const float4*)b4, batch, out);
    gnn_div<<<(NUM_GRAPHS * HID + TB - 1) / TB, TB>>>(out);
}

// round 15
// speedup vs baseline: 1.0557x; 1.0077x over previous
#include <cuda_runtime.h>

#define N_NODES    100000
#define N_EDGES    3200000
#define NUM_GRAPHS 128
#define HID        64
#define IN_DIM     15
#define NBLK       ((N_NODES + 255) / 256)   // scan blocks
#define NPB        96                        // nodes per linear block

// ---------------- scratch (device globals; no allocation allowed) -----------
// hs: 32 x bf16x2 per node (64 cols). +1 zero pad row for OOB gather lanes.
__device__ __align__(16) unsigned g_hs[(N_NODES + 1) * 32];
// xs: 8 x bf16x2 per node (16 cols, 15 real). +1 zero pad row.
__device__ __align__(16) unsigned g_xs[(N_NODES + 1) * 8];
__device__ __align__(16) float    g_aggA[N_NODES * HID];
__device__ __align__(16) float    g_aggB[N_NODES * HID];
__device__ int   g_csrc [N_EDGES];   // CSR (by dst): source node per slot
__device__ int   g_edeg  [N_NODES];
__device__ int   g_pre   [N_NODES];
__device__ int   g_rowptr[N_NODES];
__device__ int   g_fill  [N_NODES];
__device__ int   g_bsum[NBLK];
__device__ int   g_boff[NBLK];
__device__ float g_dis[N_NODES];
__device__ float g_cnt[NUM_GRAPHS];
__device__ int   g_e32;
__device__ int   g_b32;

// ---------------- packed f32x2 helpers ---------------------------------------
__device__ __forceinline__ unsigned long long fma2(unsigned long long a,
                                                   unsigned long long b,
                                                   unsigned long long c) {
    unsigned long long d;
    asm("fma.rn.f32x2 %0, %1, %2, %3;" : "=l"(d) : "l"(a), "l"(b), "l"(c));
    return d;
}
__device__ __forceinline__ unsigned long long pack2(float x) {
    unsigned long long d;
    asm("mov.b64 %0, {%1, %1};" : "=l"(d) : "f"(x));
    return d;
}

__device__ __forceinline__ int edge_at(const void* edges, long long i) {
    return g_e32 ? ((const int*)edges)[i] : (int)((const long long*)edges)[i];
}
__device__ __forceinline__ int batch_at(const void* batch, int v) {
    return g_b32 ? ((const int*)batch)[v] : (int)((const long long*)batch)[v];
}

// ---------------- init: deg zero + pad rows + out zero + dtype detect --------
__global__ void gnn_init(const void* edges, const void* batch,
                         float* __restrict__ out) {
    int v = blockIdx.x * blockDim.x + threadIdx.x;
    if (v < N_NODES) g_edeg[v] = 0;
    if (v < NUM_GRAPHS * HID) out[v] = 0.0f;
    if (v < NUM_GRAPHS) g_cnt[v] = 0.0f;
    if (blockIdx.x == 0 && threadIdx.x < 32)   // zero hs pad row
        g_hs[N_NODES * 32 + threadIdx.x] = 0u;
    if (blockIdx.x == 1 && threadIdx.x < 8)    // zero xs pad row
        g_xs[N_NODES * 8 + threadIdx.x] = 0u;
    if (blockIdx.x == gridDim.x - 1) {          // dtype detection
        __shared__ int se, sb;
        if (threadIdx.x == 0) { se = 0; sb = 0; }
        __syncthreads();
        for (int i = threadIdx.x; i < 2048; i += 256) {
            long long vi = (long long)i * (N_EDGES / 2048);
            long long x = ((const long long*)edges)[vi];
            if (x < 0 || x >= N_NODES) { atomicOr(&se, 1); break; }
        }
        for (int i = threadIdx.x; i < 2048; i += 256) {
            long long vi = (long long)i * ((N_NODES / 2) / 2048);
            long long x = ((const long long*)batch)[vi];
            if (x < 0 || x >= NUM_GRAPHS) { atomicOr(&sb, 1); break; }
        }
        __syncthreads();
        if (threadIdx.x == 0) { g_e32 = se; g_b32 = sb; }
    }
}

// ---------------- degree count ------------------------------------------------
__global__ void gnn_deg_count(const void* __restrict__ edges) {
    int e = blockIdx.x * blockDim.x + threadIdx.x;
    if (e < N_EDGES) {
        int d = edge_at(edges, (long long)N_EDGES + e);
        atomicAdd(&g_edeg[d], 1);
    }
}

// ---------------- dis + xs pack (fused; same per-node work) ------------------
__global__ void gnn_dis_xs(const float* __restrict__ x) {
    int v = blockIdx.x * blockDim.x + threadIdx.x;
    if (v >= N_NODES) return;
    float d  = (float)(g_edeg[v] + 1);   // + self loop
    float ds = rsqrtf(d);
    g_dis[v] = ds;
    unsigned r[8];
#pragma unroll
    for (int j = 0; j < 8; j++) {
        float a = x[v * IN_DIM + 2 * j] * ds;
        float b = (2 * j + 1 < IN_DIM) ? x[v * IN_DIM + 2 * j + 1] * ds : 0.0f;
        asm("cvt.rn.bf16x2.f32 %0, %1, %2;" : "=r"(r[j]) : "f"(b), "f"(a));
    }
    uint4* dst = (uint4*)&g_xs[v * 8];
    dst[0] = make_uint4(r[0], r[1], r[2], r[3]);
    dst[1] = make_uint4(r[4], r[5], r[6], r[7]);
}

// ---------------- exclusive scan of g_edeg -> g_rowptr -----------------------
__global__ void gnn_scan1() {
    __shared__ int s[256];
    int t = threadIdx.x;
    int i = blockIdx.x * 256 + t;
    int v = (i < N_NODES) ? g_edeg[i] : 0;
    s[t] = v; __syncthreads();
    for (int off = 1; off < 256; off <<= 1) {
        int add = (t >= off) ? s[t - off] : 0;
        __syncthreads();
        s[t] += add;
        __syncthreads();
    }
    if (i < N_NODES) g_pre[i] = s[t] - v;
    if (t == 255) g_bsum[blockIdx.x] = s[255];
}

__global__ void gnn_scan2() {
    __shared__ int s[512];
    int t = threadIdx.x;
    int v = (t < NBLK) ? g_bsum[t] : 0;
    s[t] = v; __syncthreads();
    for (int off = 1; off < 512; off <<= 1) {
        int add = (t >= off) ? s[t - off] : 0;
        __syncthreads();
        s[t] += add;
        __syncthreads();
    }
    if (t < NBLK) g_boff[t] = s[t] - v;
}

__global__ void gnn_scan3() {
    int i = blockIdx.x * blockDim.x + threadIdx.x;
    if (i < N_NODES) {
        g_rowptr[i] = g_pre[i] + g_boff[blockIdx.x];
        g_fill[i]   = 0;
    }
}

// ---------------- CSR fill ----------------------------------------------------
__global__ void gnn_csr_fill(const void* __restrict__ edges) {
    int e = blockIdx.x * blockDim.x + threadIdx.x;
    if (e < N_EDGES) {
        int s = edge_at(edges, e);
        int d = edge_at(edges, (long long)N_EDGES + e);
        int slot = g_rowptr[d] + atomicAdd(&g_fill[d], 1);
        g_csrc[slot] = s;
    }
}

// ---------------- linear (f32x2 packed FMA, template modes) ------------------
// K: inner dim; INS: input row stride; PRE: apply bias_prev+relu on input;
// F32OUT: write fp32 64-dim rows (no dis scale) instead of bf16 messages.
template <int K, int INS, bool PRE, bool F32OUT>
__global__ void __launch_bounds__(256) gnn_linear(const float* __restrict__ in,
                                                  const float* __restrict__ W,
                                                  const float* __restrict__ bias_prev,
                                                  unsigned* __restrict__ hs) {
    constexpr int SR = (K == 64) ? 68 : 20;   // padded row stride (words)
    constexpr int K4 = K / 4;
    __shared__ float Wsh[K * HID];
    __shared__ float insh[NPB * SR];
    __shared__ float bsh[K];
    const int tid  = threadIdx.x;
    const int base = blockIdx.x * NPB;

    for (int i = tid; i < K * HID; i += 256) Wsh[i] = W[i];
    if (PRE) for (int i = tid; i < K; i += 256) bsh[i] = bias_prev[i];
    __syncthreads();

    for (int i = tid; i < NPB * K; i += 256) {
        int n = i / K;
        int k = i - n * K;
        int v = base + n;
        float val = 0.0f;
        if (v < N_NODES) {
            val = in[v * INS + k];
            if (PRE) val = fmaxf(val + bsh[k], 0.0f);
        }
        insh[n * SR + k] = val;
    }
    __syncthreads();

    const int ng = tid >> 3;          // 0..31, 3 nodes each
    const int cb = (tid & 7) * 8;     // col block (8 cols = 4 packed pairs)
    unsigned long long accp[3][4];
#pragma unroll
    for (int i = 0; i < 3; i++)
#pragma unroll
        for (int j = 0; j < 4; j++) accp[i][j] = 0ull;

#pragma unroll
    for (int k4 = 0; k4 < K4; k4++) {
        float4 a0 = *(const float4*)&insh[(ng * 3 + 0) * SR + k4 * 4];
        float4 a1 = *(const float4*)&insh[(ng * 3 + 1) * SR + k4 * 4];
        float4 a2 = *(const float4*)&insh[(ng * 3 + 2) * SR + k4 * 4];
#pragma unroll
        for (int t = 0; t < 4; t++) {
            int k = k4 * 4 + t;
            ulonglong2 w0 = *(const ulonglong2*)&Wsh[k * HID + cb];
            ulonglong2 w1 = *(const ulonglong2*)&Wsh[k * HID + cb + 4];
            float av0 = (t == 0) ? a0.x : (t == 1) ? a0.y : (t == 2) ? a0.z : a0.w;
            float av1 = (t == 0) ? a1.x : (t == 1) ? a1.y : (t == 2) ? a1.z : a1.w;
            float av2 = (t == 0) ? a2.x : (t == 1) ? a2.y : (t == 2) ? a2.z : a2.w;
            unsigned long long p0 = pack2(av0), p1 = pack2(av1), p2 = pack2(av2);
            accp[0][0] = fma2(p0, w0.x, accp[0][0]);
            accp[0][1] = fma2(p0, w0.y, accp[0][1]);
            accp[0][2] = fma2(p0, w1.x, accp[0][2]);
            accp[0][3] = fma2(p0, w1.y, accp[0][3]);
            accp[1][0] = fma2(p1, w0.x, accp[1][0]);
            accp[1][1] = fma2(p1, w0.y, accp[1][1]);
            accp[1][2] = fma2(p1, w1.x, accp[1][2]);
            accp[1][3] = fma2(p1, w1.y, accp[1][3]);
            accp[2][0] = fma2(p2, w0.x, accp[2][0]);
            accp[2][1] = fma2(p2, w0.y, accp[2][1]);
            accp[2][2] = fma2(p2, w1.x, accp[2][2]);
            accp[2][3] = fma2(p2, w1.y, accp[2][3]);
        }
    }
#pragma unroll
    for (int k = K4 * 4; k < K; k++) {   // K tail (K=15 only)
        ulonglong2 w0 = *(const ulonglong2*)&Wsh[k * HID + cb];
        ulonglong2 w1 = *(const ulonglong2*)&Wsh[k * HID + cb + 4];
#pragma unroll
        for (int i = 0; i < 3; i++) {
            unsigned long long p = pack2(insh[(ng * 3 + i) * SR + k]);
            accp[i][0] = fma2(p, w0.x, accp[i][0]);
            accp[i][1] = fma2(p, w0.y, accp[i][1]);
            accp[i][2] = fma2(p, w1.x, accp[i][2]);
            accp[i][3] = fma2(p, w1.y, accp[i][3]);
        }
    }

#pragma unroll
    for (int i = 0; i < 3; i++) {
        int v = base + ng * 3 + i;
        if (v < N_NODES) {
            if (F32OUT) {
                float* o = (float*)hs;
#pragma unroll
                for (int j = 0; j < 4; j++)
                    *(unsigned long long*)&o[v * HID + cb + 2 * j] = accp[i][j];
            } else {
                float ds = g_dis[v];
#pragma unroll
                for (int j = 0; j < 4; j++) {
                    unsigned long long p = accp[i][j];
                    float fl = __uint_as_float((unsigned)(p & 0xffffffffull)) * ds;
                    float fh = __uint_as_float((unsigned)(p >> 32)) * ds;
                    unsigned r;
                    asm("cvt.rn.bf16x2.f32 %0, %1, %2;" : "=r"(r) : "f"(fh), "f"(fl));
                    hs[v * 32 + (cb >> 1) + j] = r;
                }
            }
        }
    }
}

// ---------------- gather16: aggx[v] = dis[v]*(sum_e xs[src] + xs[v]) ---------
__global__ void __launch_bounds__(256) gnn_gather16(const uint4* __restrict__ xs4,
                                                    float4* __restrict__ aggx4) {
    int warp = (blockIdx.x * blockDim.x + threadIdx.x) >> 5;
    int lane = threadIdx.x & 31;
    if (warp >= N_NODES) return;
    const int v  = warp;
    const int sg = lane >> 1;   // subgroup 0..15 (edge slot)
    const int p  = lane & 1;    // 16B-chunk position within 32B row
    const int beg = g_rowptr[v];
    const int end = beg + g_edeg[v];

    float acc[8];
#pragma unroll
    for (int i = 0; i < 8; i++) acc[i] = 0.0f;

    {   // self term: subgroup 0 only
        uint4 hv = xs4[v * 2 + p];
        if (sg == 0) {
            acc[0] += __uint_as_float(hv.x << 16);
            acc[1] += __uint_as_float(hv.x & 0xffff0000u);
            acc[2] += __uint_as_float(hv.y << 16);
            acc[3] += __uint_as_float(hv.y & 0xffff0000u);
            acc[4] += __uint_as_float(hv.z << 16);
            acc[5] += __uint_as_float(hv.z & 0xffff0000u);
            acc[6] += __uint_as_float(hv.w << 16);
            acc[7] += __uint_as_float(hv.w & 0xffff0000u);
        }
    }

    for (int base = beg; base < end; base += 32) {
        int idx = base + lane;
        int s = (idx < end) ? g_csrc[idx] : N_NODES;   // pad row (zeros) if OOB
        const int iters = (min(32, end - base) + 15) >> 4;  // 1 or 2
#pragma unroll
        for (int j = 0; j < 2; j++) {
            if (j < iters) {
                int ss = __shfl_sync(0xffffffffu, s, j * 16 + sg);
                uint4 hh = xs4[ss * 2 + p];
                acc[0] += __uint_as_float(hh.x << 16);
                acc[1] += __uint_as_float(hh.x & 0xffff0000u);
                acc[2] += __uint_as_float(hh.y << 16);
                acc[3] += __uint_as_float(hh.y & 0xffff0000u);
                acc[4] += __uint_as_float(hh.z << 16);
                acc[5] += __uint_as_float(hh.z & 0xffff0000u);
                acc[6] += __uint_as_float(hh.w << 16);
                acc[7] += __uint_as_float(hh.w & 0xffff0000u);
            }
        }
    }

#pragma unroll
    for (int i = 0; i < 8; i++) {
        acc[i] += __shfl_xor_sync(0xffffffffu, acc[i], 2);
        acc[i] += __shfl_xor_sync(0xffffffffu, acc[i], 4);
        acc[i] += __shfl_xor_sync(0xffffffffu, acc[i], 8);
        acc[i] += __shfl_xor_sync(0xffffffffu, acc[i], 16);
    }

    float ds = g_dis[v];
    if (sg == 0) {   // lanes 0,1 write cols p*8 .. p*8+7 (row stride 16 floats)
        aggx4[v * 4 + p * 2]     = make_float4(acc[0] * ds, acc[1] * ds, acc[2] * ds, acc[3] * ds);
        aggx4[v * 4 + p * 2 + 1] = make_float4(acc[4] * ds, acc[5] * ds, acc[6] * ds, acc[7] * ds);
    }
}

// ---------------- gather (64-col bf16): EXACT R11/R13/R14 body ----------------
__global__ void __launch_bounds__(256) gnn_gather(const uint4* __restrict__ hs4,
                                                  float4* __restrict__ agg4) {
    int warp = (blockIdx.x * blockDim.x + threadIdx.x) >> 5;
    int lane = threadIdx.x & 31;
    if (warp >= N_NODES) return;
    const int v  = warp;
    const int sg = lane >> 3;   // subgroup 0..3
    const int p  = lane & 7;    // 16B-chunk position within row
    const int beg = g_rowptr[v];
    const int end = beg + g_edeg[v];

    float acc[8];
#pragma unroll
    for (int i = 0; i < 8; i++) acc[i] = 0.0f;

    {
        uint4 hv = hs4[v * 8 + p];
        if (sg == 0) {
            acc[0] += __uint_as_float(hv.x << 16);
            acc[1] += __uint_as_float(hv.x & 0xffff0000u);
            acc[2] += __uint_as_float(hv.y << 16);
            acc[3] += __uint_as_float(hv.y & 0xffff0000u);
            acc[4] += __uint_as_float(hv.z << 16);
            acc[5] += __uint_as_float(hv.z & 0xffff0000u);
            acc[6] += __uint_as_float(hv.w << 16);
            acc[7] += __uint_as_float(hv.w & 0xffff0000u);
        }
    }

    for (int base = beg; base < end; base += 32) {
        int idx = base + lane;
        int s = (idx < end) ? g_csrc[idx] : N_NODES;
        const int iters = (min(32, end - base) + 3) >> 2;
#pragma unroll
        for (int j = 0; j < 8; j++) {
            if (j < iters) {
                int ss = __shfl_sync(0xffffffffu, s, j * 4 + sg);
                uint4 hh = hs4[ss * 8 + p];
                acc[0] += __uint_as_float(hh.x << 16);
                acc[1] += __uint_as_float(hh.x & 0xffff0000u);
                acc[2] += __uint_as_float(hh.y << 16);
                acc[3] += __uint_as_float(hh.y & 0xffff0000u);
                acc[4] += __uint_as_float(hh.z << 16);
                acc[5] += __uint_as_float(hh.z & 0xffff0000u);
                acc[6] += __uint_as_float(hh.w << 16);
                acc[7] += __uint_as_float(hh.w & 0xffff0000u);
            }
        }
    }

#pragma unroll
    for (int i = 0; i < 8; i++) {
        acc[i] += __shfl_xor_sync(0xffffffffu, acc[i], 8);
        acc[i] += __shfl_xor_sync(0xffffffffu, acc[i], 16);
    }

    float ds = g_dis[v];
    if (sg == 0) {
        float4 r0 = make_float4(acc[0] * ds, acc[1] * ds, acc[2] * ds, acc[3] * ds);
        float4 r1 = make_float4(acc[4] * ds, acc[5] * ds, acc[6] * ds, acc[7] * ds);
        agg4[v * 16 + p * 2]     = r0;
        agg4[v * 16 + p * 2 + 1] = r1;
    }
}

// ---------------- pooling ----------------------------------------------------
__global__ void gnn_pool(const float4* __restrict__ agg,
                         const float4* __restrict__ bias4,
                         const void* __restrict__ batch,
                         float* __restrict__ out) {
    unsigned idx = blockIdx.x * blockDim.x + threadIdx.x;
    int v = idx >> 4;
    int c = idx & 15;
    if (v >= N_NODES) return;
    int g = batch_at(batch, v);
    float4 a = agg[v * 16 + c];
    float4 b = bias4[c];
    float x0 = fmaxf(a.x + b.x, 0.0f);
    float x1 = fmaxf(a.y + b.y, 0.0f);
    float x2 = fmaxf(a.z + b.z, 0.0f);
    float x3 = fmaxf(a.w + b.w, 0.0f);
    float* p = &out[g * HID + c * 4];
    asm volatile("red.global.add.v4.f32 [%0], {%1, %2, %3, %4};"
                 :: "l"(p), "f"(x0), "f"(x1), "f"(x2), "f"(x3)
                 : "memory");
    if (c == 0) atomicAdd(&g_cnt[g], 1.0f);
}

__global__ void gnn_div(float* __restrict__ out) {
    int i = blockIdx.x * blockDim.x + threadIdx.x;
    if (i < NUM_GRAPHS * HID) {
        int g = i >> 6;
        out[i] /= fmaxf(g_cnt[g], 1.0f);
    }
}

// ---------------- host -------------------------------------------------------
extern "C" void kernel_launch(void* const* d_in, const int* in_sizes, int n_in,
                              void* d_out, int out_size) {
    const float* x     = (const float*)d_in[0];
    const float* w1    = (const float*)d_in[1];
    const float* b1    = (const float*)d_in[2];
    const float* w2    = (const float*)d_in[3];
    const float* b2    = (const float*)d_in[4];
    const float* w3    = (const float*)d_in[5];
    const float* b3    = (const float*)d_in[6];
    const float* w4    = (const float*)d_in[7];
    const float* b4    = (const float*)d_in[8];
    const void*  edges = d_in[9];
    const void*  batch = d_in[10];
    float* out = (float*)d_out;

    void *p_hs, *p_xs, *p_aggA, *p_aggB;
    cudaGetSymbolAddress(&p_hs,   g_hs);
    cudaGetSymbolAddress(&p_xs,   g_xs);
    cudaGetSymbolAddress(&p_aggA, g_aggA);
    cudaGetSymbolAddress(&p_aggB, g_aggB);
    unsigned* hs   = (unsigned*)p_hs;
    unsigned* xs   = (unsigned*)p_xs;
    float*    aggA = (float*)p_aggA;
    float*    aggB = (float*)p_aggB;

    const int TB = 256;
    const int nodeB = (N_NODES + TB - 1) / TB;
    const int edgeB = (N_EDGES + TB - 1) / TB;

    gnn_init     <<<nodeB, TB>>>(edges, batch, out);
    gnn_deg_count<<<edgeB, TB>>>(edges);
    gnn_dis_xs   <<<nodeB, TB>>>(x);
    gnn_scan1    <<<NBLK, 256>>>();
    gnn_scan2    <<<1, 512>>>();
    gnn_scan3    <<<NBLK, 256>>>();
    gnn_csr_fill <<<edgeB, TB>>>(edges);

    const int linB = (N_NODES + NPB - 1) / NPB;
    const int gatB = (N_NODES * 32 + TB - 1) / TB;

    // layer 1: aggx = Â·xs (16-dim, into aggB), then aggA = aggx @ W1
    gnn_gather16<<<gatB, TB>>>((const uint4*)xs, (float4*)aggB);
    gnn_linear<IN_DIM, 16, false, true><<<linB, TB>>>(aggB, w1, nullptr,
                                                      (unsigned*)aggA);
    // layer 2
    gnn_linear<HID, HID, true, false><<<linB, TB>>>(aggA, w2, b1, hs);
    gnn_gather<<<gatB, TB>>>((const uint4*)hs, (float4*)aggB);
    // layer 3
    gnn_linear<HID, HID, true, false><<<linB, TB>>>(aggB, w3, b2, hs);
    gnn_gather<<<gatB, TB>>>((const uint4*)hs, (float4*)aggA);
    // layer 4
    gnn_linear<HID, HID, true, false><<<linB, TB>>>(aggA, w4, b3, hs);
    gnn_gather<<<gatB, TB>>>((const uint4*)hs, (float4*)aggB);

    // pooling
    const unsigned poolT = (unsigned)N_NODES * 16u;
    gnn_pool<<<(int)((poolT + TB - 1) / TB), TB>>>(
        (const float4*)aggB, (const float4*)b4, batch, out);
    gnn_div<<<(NUM_GRAPHS * HID + TB - 1) / TB, TB>>>(out);
}

// round 16
// speedup vs baseline: 1.0730x; 1.0164x over previous
#include <cuda_runtime.h>

#define N_NODES    100000
#define N_EDGES    3200000
#define NUM_GRAPHS 128
#define HID        64
#define IN_DIM     15
#define NBLK       ((N_NODES + 255) / 256)   // scan blocks
#define NPB        96                        // nodes per linear block

// ---------------- scratch (device globals; no allocation allowed) -----------
__device__ __align__(16) unsigned g_hs[(N_NODES + 1) * 32];
__device__ __align__(16) unsigned g_xs[(N_NODES + 1) * 8];
__device__ __align__(16) float    g_aggA[N_NODES * HID];
__device__ __align__(16) float    g_aggB[N_NODES * HID];
__device__ int   g_csrc [N_EDGES];   // CSR (by dst): source node per slot
__device__ int   g_edeg  [N_NODES];
__device__ int   g_pre   [N_NODES];  // per-block exclusive prescan
__device__ int   g_fill  [N_NODES];
__device__ int   g_bsum[NBLK];
__device__ int   g_boff[NBLK];       // block offsets: rowptr(v)=g_pre[v]+g_boff[v>>8]
__device__ float g_dis[N_NODES];
__device__ float g_cnt[NUM_GRAPHS];
__device__ float g_rcnt[NUM_GRAPHS];
__device__ int   g_e32;
__device__ int   g_b32;

// ---------------- packed f32x2 helpers ---------------------------------------
__device__ __forceinline__ unsigned long long fma2(unsigned long long a,
                                                   unsigned long long b,
                                                   unsigned long long c) {
    unsigned long long d;
    asm("fma.rn.f32x2 %0, %1, %2, %3;" : "=l"(d) : "l"(a), "l"(b), "l"(c));
    return d;
}
__device__ __forceinline__ unsigned long long pack2(float x) {
    unsigned long long d;
    asm("mov.b64 %0, {%1, %1};" : "=l"(d) : "f"(x));
    return d;
}

__device__ __forceinline__ int edge_at(const void* edges, long long i) {
    return g_e32 ? ((const int*)edges)[i] : (int)((const long long*)edges)[i];
}
__device__ __forceinline__ int batch_at(const void* batch, int v) {
    return g_b32 ? ((const int*)batch)[v] : (int)((const long long*)batch)[v];
}
__device__ __forceinline__ int rowptr_of(int v) {
    return g_pre[v] + g_boff[v >> 8];
}

// ---------------- init: zero deg/fill/cnt/out + pad rows + dtype detect ------
__global__ void gnn_init(const void* edges, const void* batch,
                         float* __restrict__ out) {
    int v = blockIdx.x * blockDim.x + threadIdx.x;
    if (v < N_NODES) { g_edeg[v] = 0; g_fill[v] = 0; }
    if (v < NUM_GRAPHS * HID) out[v] = 0.0f;
    if (v < NUM_GRAPHS) g_cnt[v] = 0.0f;
    if (blockIdx.x == 0 && threadIdx.x < 32)   // zero hs pad row
        g_hs[N_NODES * 32 + threadIdx.x] = 0u;
    if (blockIdx.x == 1 && threadIdx.x < 8)    // zero xs pad row
        g_xs[N_NODES * 8 + threadIdx.x] = 0u;
    if (blockIdx.x == gridDim.x - 1) {          // dtype detection
        __shared__ int se, sb;
        if (threadIdx.x == 0) { se = 0; sb = 0; }
        __syncthreads();
        for (int i = threadIdx.x; i < 2048; i += 256) {
            long long vi = (long long)i * (N_EDGES / 2048);
            long long x = ((const long long*)edges)[vi];
            if (x < 0 || x >= N_NODES) { atomicOr(&se, 1); break; }
        }
        for (int i = threadIdx.x; i < 2048; i += 256) {
            long long vi = (long long)i * ((N_NODES / 2) / 2048);
            long long x = ((const long long*)batch)[vi];
            if (x < 0 || x >= NUM_GRAPHS) { atomicOr(&sb, 1); break; }
        }
        __syncthreads();
        if (threadIdx.x == 0) { g_e32 = se; g_b32 = sb; }
    }
}

// ---------------- degree count ------------------------------------------------
__global__ void gnn_deg_count(const void* __restrict__ edges) {
    int e = blockIdx.x * blockDim.x + threadIdx.x;
    if (e < N_EDGES) {
        int d = edge_at(edges, (long long)N_EDGES + e);
        atomicAdd(&g_edeg[d], 1);
    }
}

// ---------------- dis + xs pack + per-graph node count ------------------------
__global__ void gnn_dis_xs(const float* __restrict__ x,
                           const void* __restrict__ batch) {
    int v = blockIdx.x * blockDim.x + threadIdx.x;
    if (v >= N_NODES) return;
    float d  = (float)(g_edeg[v] + 1);   // + self loop
    float ds = rsqrtf(d);
    g_dis[v] = ds;
    unsigned r[8];
#pragma unroll
    for (int j = 0; j < 8; j++) {
        float a = x[v * IN_DIM + 2 * j] * ds;
        float b = (2 * j + 1 < IN_DIM) ? x[v * IN_DIM + 2 * j + 1] * ds : 0.0f;
        asm("cvt.rn.bf16x2.f32 %0, %1, %2;" : "=r"(r[j]) : "f"(b), "f"(a));
    }
    uint4* dst = (uint4*)&g_xs[v * 8];
    dst[0] = make_uint4(r[0], r[1], r[2], r[3]);
    dst[1] = make_uint4(r[4], r[5], r[6], r[7]);
    // per-graph node count (batch sorted -> warp-uniform -> REDUX-aggregated)
    atomicAdd(&g_cnt[batch_at(batch, v)], 1.0f);
}

// ---------------- scan1 / scan2 (block-sum offsets; no scan3) ----------------
__global__ void gnn_scan1() {
    __shared__ int s[256];
    int t = threadIdx.x;
    int i = blockIdx.x * 256 + t;
    int v = (i < N_NODES) ? g_edeg[i] : 0;
    s[t] = v; __syncthreads();
    for (int off = 1; off < 256; off <<= 1) {
        int add = (t >= off) ? s[t - off] : 0;
        __syncthreads();
        s[t] += add;
        __syncthreads();
    }
    if (i < N_NODES) g_pre[i] = s[t] - v;
    if (t == 255) g_bsum[blockIdx.x] = s[255];
}

__global__ void gnn_scan2() {
    __shared__ int s[512];
    int t = threadIdx.x;
    int v = (t < NBLK) ? g_bsum[t] : 0;
    s[t] = v; __syncthreads();
    for (int off = 1; off < 512; off <<= 1) {
        int add = (t >= off) ? s[t - off] : 0;
        __syncthreads();
        s[t] += add;
        __syncthreads();
    }
    if (t < NBLK) g_boff[t] = s[t] - v;
    if (t < NUM_GRAPHS) g_rcnt[t] = 1.0f / fmaxf(g_cnt[t], 1.0f);
}

// ---------------- CSR fill (rowptr computed inline) ---------------------------
__global__ void gnn_csr_fill(const void* __restrict__ edges) {
    int e = blockIdx.x * blockDim.x + threadIdx.x;
    if (e < N_EDGES) {
        int s = edge_at(edges, e);
        int d = edge_at(edges, (long long)N_EDGES + e);
        int slot = rowptr_of(d) + atomicAdd(&g_fill[d], 1);
        g_csrc[slot] = s;
    }
}

// ---------------- linear (f32x2 packed FMA, template modes) ------------------
template <int K, int INS, bool PRE, bool F32OUT>
__global__ void __launch_bounds__(256) gnn_linear(const float* __restrict__ in,
                                                  const float* __restrict__ W,
                                                  const float* __restrict__ bias_prev,
                                                  unsigned* __restrict__ hs) {
    constexpr int SR = (K == 64) ? 68 : 20;   // padded row stride (words)
    constexpr int K4 = K / 4;
    __shared__ float Wsh[K * HID];
    __shared__ float insh[NPB * SR];
    __shared__ float bsh[K];
    const int tid  = threadIdx.x;
    const int base = blockIdx.x * NPB;

    for (int i = tid; i < K * HID; i += 256) Wsh[i] = W[i];
    if (PRE) for (int i = tid; i < K; i += 256) bsh[i] = bias_prev[i];
    __syncthreads();

    for (int i = tid; i < NPB * K; i += 256) {
        int n = i / K;
        int k = i - n * K;
        int v = base + n;
        float val = 0.0f;
        if (v < N_NODES) {
            val = in[v * INS + k];
            if (PRE) val = fmaxf(val + bsh[k], 0.0f);
        }
        insh[n * SR + k] = val;
    }
    __syncthreads();

    const int ng = tid >> 3;          // 0..31, 3 nodes each
    const int cb = (tid & 7) * 8;     // col block (8 cols = 4 packed pairs)
    unsigned long long accp[3][4];
#pragma unroll
    for (int i = 0; i < 3; i++)
#pragma unroll
        for (int j = 0; j < 4; j++) accp[i][j] = 0ull;

#pragma unroll
    for (int k4 = 0; k4 < K4; k4++) {
        float4 a0 = *(const float4*)&insh[(ng * 3 + 0) * SR + k4 * 4];
        float4 a1 = *(const float4*)&insh[(ng * 3 + 1) * SR + k4 * 4];
        float4 a2 = *(const float4*)&insh[(ng * 3 + 2) * SR + k4 * 4];
#pragma unroll
        for (int t = 0; t < 4; t++) {
            int k = k4 * 4 + t;
            ulonglong2 w0 = *(const ulonglong2*)&Wsh[k * HID + cb];
            ulonglong2 w1 = *(const ulonglong2*)&Wsh[k * HID + cb + 4];
            float av0 = (t == 0) ? a0.x : (t == 1) ? a0.y : (t == 2) ? a0.z : a0.w;
            float av1 = (t == 0) ? a1.x : (t == 1) ? a1.y : (t == 2) ? a1.z : a1.w;
            float av2 = (t == 0) ? a2.x : (t == 1) ? a2.y : (t == 2) ? a2.z : a2.w;
            unsigned long long p0 = pack2(av0), p1 = pack2(av1), p2 = pack2(av2);
            accp[0][0] = fma2(p0, w0.x, accp[0][0]);
            accp[0][1] = fma2(p0, w0.y, accp[0][1]);
            accp[0][2] = fma2(p0, w1.x, accp[0][2]);
            accp[0][3] = fma2(p0, w1.y, accp[0][3]);
            accp[1][0] = fma2(p1, w0.x, accp[1][0]);
            accp[1][1] = fma2(p1, w0.y, accp[1][1]);
            accp[1][2] = fma2(p1, w1.x, accp[1][2]);
            accp[1][3] = fma2(p1, w1.y, accp[1][3]);
            accp[2][0] = fma2(p2, w0.x, accp[2][0]);
            accp[2][1] = fma2(p2, w0.y, accp[2][1]);
            accp[2][2] = fma2(p2, w1.x, accp[2][2]);
            accp[2][3] = fma2(p2, w1.y, accp[2][3]);
        }
    }
#pragma unroll
    for (int k = K4 * 4; k < K; k++) {   // K tail (K=15 only)
        ulonglong2 w0 = *(const ulonglong2*)&Wsh[k * HID + cb];
        ulonglong2 w1 = *(const ulonglong2*)&Wsh[k * HID + cb + 4];
#pragma unroll
        for (int i = 0; i < 3; i++) {
            unsigned long long p = pack2(insh[(ng * 3 + i) * SR + k]);
            accp[i][0] = fma2(p, w0.x, accp[i][0]);
            accp[i][1] = fma2(p, w0.y, accp[i][1]);
            accp[i][2] = fma2(p, w1.x, accp[i][2]);
            accp[i][3] = fma2(p, w1.y, accp[i][3]);
        }
    }

#pragma unroll
    for (int i = 0; i < 3; i++) {
        int v = base + ng * 3 + i;
        if (v < N_NODES) {
            if (F32OUT) {
                float* o = (float*)hs;
#pragma unroll
                for (int j = 0; j < 4; j++)
                    *(unsigned long long*)&o[v * HID + cb + 2 * j] = accp[i][j];
            } else {
                float ds = g_dis[v];
#pragma unroll
                for (int j = 0; j < 4; j++) {
                    unsigned long long p = accp[i][j];
                    float fl = __uint_as_float((unsigned)(p & 0xffffffffull)) * ds;
                    float fh = __uint_as_float((unsigned)(p >> 32)) * ds;
                    unsigned r;
                    asm("cvt.rn.bf16x2.f32 %0, %1, %2;" : "=r"(r) : "f"(fh), "f"(fl));
                    hs[v * 32 + (cb >> 1) + j] = r;
                }
            }
        }
    }
}

// ---------------- gather16: aggx[v] = dis[v]*(sum_e xs[src] + xs[v]) ---------
__global__ void __launch_bounds__(256) gnn_gather16(const uint4* __restrict__ xs4,
                                                    float4* __restrict__ aggx4) {
    int warp = (blockIdx.x * blockDim.x + threadIdx.x) >> 5;
    int lane = threadIdx.x & 31;
    if (warp >= N_NODES) return;
    const int v  = warp;
    const int sg = lane >> 1;
    const int p  = lane & 1;
    const int beg = rowptr_of(v);
    const int end = beg + g_edeg[v];

    float acc[8];
#pragma unroll
    for (int i = 0; i < 8; i++) acc[i] = 0.0f;

    {   // self term: subgroup 0 only
        uint4 hv = xs4[v * 2 + p];
        if (sg == 0) {
            acc[0] += __uint_as_float(hv.x << 16);
            acc[1] += __uint_as_float(hv.x & 0xffff0000u);
            acc[2] += __uint_as_float(hv.y << 16);
            acc[3] += __uint_as_float(hv.y & 0xffff0000u);
            acc[4] += __uint_as_float(hv.z << 16);
            acc[5] += __uint_as_float(hv.z & 0xffff0000u);
            acc[6] += __uint_as_float(hv.w << 16);
            acc[7] += __uint_as_float(hv.w & 0xffff0000u);
        }
    }

    for (int base = beg; base < end; base += 32) {
        int idx = base + lane;
        int s = (idx < end) ? g_csrc[idx] : N_NODES;
        const int iters = (min(32, end - base) + 15) >> 4;
#pragma unroll
        for (int j = 0; j < 2; j++) {
            if (j < iters) {
                int ss = __shfl_sync(0xffffffffu, s, j * 16 + sg);
                uint4 hh = xs4[ss * 2 + p];
                acc[0] += __uint_as_float(hh.x << 16);
                acc[1] += __uint_as_float(hh.x & 0xffff0000u);
                acc[2] += __uint_as_float(hh.y << 16);
                acc[3] += __uint_as_float(hh.y & 0xffff0000u);
                acc[4] += __uint_as_float(hh.z << 16);
                acc[5] += __uint_as_float(hh.z & 0xffff0000u);
                acc[6] += __uint_as_float(hh.w << 16);
                acc[7] += __uint_as_float(hh.w & 0xffff0000u);
            }
        }
    }

#pragma unroll
    for (int i = 0; i < 8; i++) {
        acc[i] += __shfl_xor_sync(0xffffffffu, acc[i], 2);
        acc[i] += __shfl_xor_sync(0xffffffffu, acc[i], 4);
        acc[i] += __shfl_xor_sync(0xffffffffu, acc[i], 8);
        acc[i] += __shfl_xor_sync(0xffffffffu, acc[i], 16);
    }

    float ds = g_dis[v];
    if (sg == 0) {
        aggx4[v * 4 + p * 2]     = make_float4(acc[0] * ds, acc[1] * ds, acc[2] * ds, acc[3] * ds);
        aggx4[v * 4 + p * 2 + 1] = make_float4(acc[4] * ds, acc[5] * ds, acc[6] * ds, acc[7] * ds);
    }
}

// ---------------- gather (64-col bf16): R11 body with inline rowptr -----------
__global__ void __launch_bounds__(256) gnn_gather(const uint4* __restrict__ hs4,
                                                  float4* __restrict__ agg4) {
    int warp = (blockIdx.x * blockDim.x + threadIdx.x) >> 5;
    int lane = threadIdx.x & 31;
    if (warp >= N_NODES) return;
    const int v  = warp;
    const int sg = lane >> 3;
    const int p  = lane & 7;
    const int beg = rowptr_of(v);
    const int end = beg + g_edeg[v];

    float acc[8];
#pragma unroll
    for (int i = 0; i < 8; i++) acc[i] = 0.0f;

    {
        uint4 hv = hs4[v * 8 + p];
        if (sg == 0) {
            acc[0] += __uint_as_float(hv.x << 16);
            acc[1] += __uint_as_float(hv.x & 0xffff0000u);
            acc[2] += __uint_as_float(hv.y << 16);
            acc[3] += __uint_as_float(hv.y & 0xffff0000u);
            acc[4] += __uint_as_float(hv.z << 16);
            acc[5] += __uint_as_float(hv.z & 0xffff0000u);
            acc[6] += __uint_as_float(hv.w << 16);
            acc[7] += __uint_as_float(hv.w & 0xffff0000u);
        }
    }

    for (int base = beg; base < end; base += 32) {
        int idx = base + lane;
        int s = (idx < end) ? g_csrc[idx] : N_NODES;
        const int iters = (min(32, end - base) + 3) >> 2;
#pragma unroll
        for (int j = 0; j < 8; j++) {
            if (j < iters) {
                int ss = __shfl_sync(0xffffffffu, s, j * 4 + sg);
                uint4 hh = hs4[ss * 8 + p];
                acc[0] += __uint_as_float(hh.x << 16);
                acc[1] += __uint_as_float(hh.x & 0xffff0000u);
                acc[2] += __uint_as_float(hh.y << 16);
                acc[3] += __uint_as_float(hh.y & 0xffff0000u);
                acc[4] += __uint_as_float(hh.z << 16);
                acc[5] += __uint_as_float(hh.z & 0xffff0000u);
                acc[6] += __uint_as_float(hh.w << 16);
                acc[7] += __uint_as_float(hh.w & 0xffff0000u);
            }
        }
    }

#pragma unroll
    for (int i = 0; i < 8; i++) {
        acc[i] += __shfl_xor_sync(0xffffffffu, acc[i], 8);
        acc[i] += __shfl_xor_sync(0xffffffffu, acc[i], 16);
    }

    float ds = g_dis[v];
    if (sg == 0) {
        float4 r0 = make_float4(acc[0] * ds, acc[1] * ds, acc[2] * ds, acc[3] * ds);
        float4 r1 = make_float4(acc[4] * ds, acc[5] * ds, acc[6] * ds, acc[7] * ds);
        agg4[v * 16 + p * 2]     = r0;
        agg4[v * 16 + p * 2 + 1] = r1;
    }
}

// ---------------- pooling (mean folded in via rcnt; no count atomics) --------
__global__ void gnn_pool(const float4* __restrict__ agg,
                         const float4* __restrict__ bias4,
                         const void* __restrict__ batch,
                         float* __restrict__ out) {
    unsigned idx = blockIdx.x * blockDim.x + threadIdx.x;
    int v = idx >> 4;
    int c = idx & 15;
    if (v >= N_NODES) return;
    int g = batch_at(batch, v);
    float rc = g_rcnt[g];
    float4 a = agg[v * 16 + c];
    float4 b = bias4[c];
    float x0 = fmaxf(a.x + b.x, 0.0f) * rc;
    float x1 = fmaxf(a.y + b.y, 0.0f) * rc;
    float x2 = fmaxf(a.z + b.z, 0.0f) * rc;
    float x3 = fmaxf(a.w + b.w, 0.0f) * rc;
    float* p = &out[g * HID + c * 4];
    asm volatile("red.global.add.v4.f32 [%0], {%1, %2, %3, %4};"
                 :: "l"(p), "f"(x0), "f"(x1), "f"(x2), "f"(x3)
                 : "memory");
}

// ---------------- host -------------------------------------------------------
extern "C" void kernel_launch(void* const* d_in, const int* in_sizes, int n_in,
                              void* d_out, int out_size) {
    const float* x     = (const float*)d_in[0];
    const float* w1    = (const float*)d_in[1];
    const float* b1    = (const float*)d_in[2];
    const float* w2    = (const float*)d_in[3];
    const float* b2    = (const float*)d_in[4];
    const float* w3    = (const float*)d_in[5];
    const float* b3    = (const float*)d_in[6];
    const float* w4    = (const float*)d_in[7];
    const float* b4    = (const float*)d_in[8];
    const void*  edges = d_in[9];
    const void*  batch = d_in[10];
    float* out = (float*)d_out;

    void *p_hs, *p_xs, *p_aggA, *p_aggB;
    cudaGetSymbolAddress(&p_hs,   g_hs);
    cudaGetSymbolAddress(&p_xs,   g_xs);
    cudaGetSymbolAddress(&p_aggA, g_aggA);
    cudaGetSymbolAddress(&p_aggB, g_aggB);
    unsigned* hs   = (unsigned*)p_hs;
    unsigned* xs   = (unsigned*)p_xs;
    float*    aggA = (float*)p_aggA;
    float*    aggB = (float*)p_aggB;

    const int TB = 256;
    const int nodeB = (N_NODES + TB - 1) / TB;
    const int edgeB = (N_EDGES + TB - 1) / TB;

    gnn_init     <<<nodeB, TB>>>(edges, batch, out);
    gnn_deg_count<<<edgeB, TB>>>(edges);
    gnn_dis_xs   <<<nodeB, TB>>>(x, batch);
    gnn_scan1    <<<NBLK, 256>>>();
    gnn_scan2    <<<1, 512>>>();
    gnn_csr_fill <<<edgeB, TB>>>(edges);

    const int linB = (N_NODES + NPB - 1) / NPB;
    const int gatB = (N_NODES * 32 + TB - 1) / TB;

    // layer 1: aggx = Â·xs (16-dim, into aggB), then aggA = aggx @ W1
    gnn_gather16<<<gatB, TB>>>((const uint4*)xs, (float4*)aggB);
    gnn_linear<IN_DIM, 16, false, true><<<linB, TB>>>(aggB, w1, nullptr,
                                                      (unsigned*)aggA);
    // layer 2
    gnn_linear<HID, HID, true, false><<<linB, TB>>>(aggA, w2, b1, hs);
    gnn_gather<<<gatB, TB>>>((const uint4*)hs, (float4*)aggB);
    // layer 3
    gnn_linear<HID, HID, true, false><<<linB, TB>>>(aggB, w3, b2, hs);
    gnn_gather<<<gatB, TB>>>((const uint4*)hs, (float4*)aggA);
    // layer 4
    gnn_linear<HID, HID, true, false><<<linB, TB>>>(aggA, w4, b3, hs);
    gnn_gather<<<gatB, TB>>>((const uint4*)hs, (float4*)aggB);

    // pooling (mean via rcnt; no div pass)
    const unsigned poolT = (unsigned)N_NODES * 16u;
    gnn_pool<<<(int)((poolT + TB - 1) / TB), TB>>>(
        (const float4*)aggB, (const float4*)b4, batch, out);
}